// round 12
// baseline (speedup 1.0000x reference)
#include <cuda_runtime.h>
#include <cuda_fp16.h>
#include <cstdint>

#define B_SZ 4
#define L_SZ 2048
#define DM   1024
#define H_N  16
#define DK   64
#define BH   64
#define ROWS 8192
#define EPS_Z 1e-8f
#define NSPLIT 8

// ---------------- scratch ----------------------------------------------------
__device__ __half g_Wh[4][DM * DM];
__device__ __half g_Ah[3][ROWS * DM];
__device__ __half g_Qp[ROWS * DM];
__device__ __half g_Kp[ROWS * DM];
__device__ __half g_Vp[ROWS * DM];
__device__ __half g_Mid[ROWS * DM];
__device__ float  g_kv_part[NSPLIT * BH * DK * DK];
__device__ float  g_ks_part[NSPLIT * BH * DK];
__device__ float  g_KV[BH * DK * DK];
__device__ float  g_Ksum[BH * DK];

// ---------------- helpers ----------------------------------------------------
__device__ __forceinline__ float feature_map(float x) {
    return x > 0.0f ? x + 1.0f : expf(x);
}
__device__ __forceinline__ uint32_t su32(const void* p) {
    uint32_t a;
    asm("{ .reg .u64 t; cvta.to.shared.u64 t, %1; cvt.u32.u64 %0, t; }" : "=r"(a) : "l"(p));
    return a;
}
#define CP16(s, g) asm volatile("cp.async.cg.shared.global [%0], [%1], 16;" :: "r"(s), "l"(g))
#define CP_COMMIT() asm volatile("cp.async.commit_group;")
#define SWZ(o) ((o) ^ (((o) >> 3) & 0x70))

__device__ __forceinline__ void ldm_x4(uint32_t* r, uint32_t addr) {
    asm volatile("ldmatrix.sync.aligned.m8n8.x4.shared.b16 {%0,%1,%2,%3}, [%4];"
                 : "=r"(r[0]), "=r"(r[1]), "=r"(r[2]), "=r"(r[3]) : "r"(addr));
}
__device__ __forceinline__ void ldm_x4_t(uint32_t* r, uint32_t addr) {
    asm volatile("ldmatrix.sync.aligned.m8n8.x4.trans.shared.b16 {%0,%1,%2,%3}, [%4];"
                 : "=r"(r[0]), "=r"(r[1]), "=r"(r[2]), "=r"(r[3]) : "r"(addr));
}
__device__ __forceinline__ void mma_f16(float* d, const uint32_t* a, const uint32_t* b) {
    asm volatile(
        "mma.sync.aligned.m16n8k16.row.col.f32.f16.f16.f32 "
        "{%0,%1,%2,%3},{%4,%5,%6,%7},{%8,%9},{%0,%1,%2,%3};\n"
        : "+f"(d[0]), "+f"(d[1]), "+f"(d[2]), "+f"(d[3])
        : "r"(a[0]), "r"(a[1]), "r"(a[2]), "r"(a[3]),
          "r"(b[0]), "r"(b[1]));
}

// ---------------- fp16 GEMM core (R11): BM=128 BN=128 BK=64, 256 thr ---------
#define GBM 128
#define GBN 128
#define ABYTES (GBM * 128)        // 16384
#define BBYTES (GBN * 128)        // 16384
#define STAGEB (ABYTES + BBYTES)  // 32768
#define GSMEM  (2 * STAGEB)       // 65536

template <int OUTK>
__device__ __forceinline__
void gemm_core(const __half* __restrict__ A, const __half* __restrict__ W,
               void* __restrict__ Cv, int act, int bm0, int bn0, char* sm)
{
    const int tid = threadIdx.x;
    const int wid = tid >> 5;
    const int lane = tid & 31;
    const int wm = wid >> 1;      // 0..3
    const int wn = wid & 1;       // 0..1
    const int gid = lane >> 2;
    const int tig = lane & 3;

    const __half* Ag = A + (size_t)bm0 * DM;
    const __half* Wg = W + (size_t)bn0 * DM;
    const uint32_t sbase = su32(sm);

    float acc[2][8][4];
#pragma unroll
    for (int mi = 0; mi < 2; mi++)
#pragma unroll
        for (int ni = 0; ni < 8; ni++)
#pragma unroll
            for (int c = 0; c < 4; c++) acc[mi][ni][c] = 0.0f;

    auto load_tile = [&](int stg, int k0) {
        const uint32_t ab = sbase + stg * STAGEB;
        const uint32_t bb = ab + ABYTES;
#pragma unroll
        for (int j = 0; j < 4; j++) {
            int i = tid + j * 256;
            int r = i >> 3, q = i & 7;
            CP16(ab + SWZ(r * 128 + q * 16), Ag + (size_t)r * DM + k0 + q * 8);
        }
#pragma unroll
        for (int j = 0; j < 4; j++) {
            int i = tid + j * 256;
            int r = i >> 3, q = i & 7;
            CP16(bb + SWZ(r * 128 + q * 16), Wg + (size_t)r * DM + k0 + q * 8);
        }
        CP_COMMIT();
    };

    const int KT = DM / 64;   // 16
    load_tile(0, 0);

    const int lrow = lane & 15;
    const int lhi  = (lane >> 4) << 4;

    for (int t = 0; t < KT; t++) {
        const int cur = t & 1;
        if (t + 1 < KT) {
            load_tile(cur ^ 1, (t + 1) * 64);
            asm volatile("cp.async.wait_group 1;");
        } else {
            asm volatile("cp.async.wait_group 0;");
        }
        __syncthreads();

        const uint32_t ab = sbase + cur * STAGEB;
        const uint32_t bb = ab + ABYTES;

#pragma unroll
        for (int ks = 0; ks < 4; ks++) {
            const int kboff = ks * 32 + lhi;
            uint32_t af[2][4];
            uint32_t bf[4][4];
#pragma unroll
            for (int mi = 0; mi < 2; mi++)
                ldm_x4(af[mi], ab + SWZ((wm * 32 + mi * 16 + lrow) * 128 + kboff));
#pragma unroll
            for (int p = 0; p < 4; p++)
                ldm_x4(bf[p], bb + SWZ((wn * 64 + p * 16 + lrow) * 128 + kboff));
#pragma unroll
            for (int mi = 0; mi < 2; mi++)
#pragma unroll
                for (int p = 0; p < 4; p++) {
                    uint32_t b0[2] = { bf[p][0], bf[p][2] };
                    uint32_t b1[2] = { bf[p][1], bf[p][3] };
                    mma_f16(acc[mi][2 * p + 0], af[mi], b0);
                    mma_f16(acc[mi][2 * p + 1], af[mi], b1);
                }
        }
        __syncthreads();
    }

#pragma unroll
    for (int mi = 0; mi < 2; mi++) {
        int r0 = bm0 + wm * 32 + mi * 16 + gid;
#pragma unroll
        for (int ni = 0; ni < 8; ni++) {
            int c0 = bn0 + wn * 64 + ni * 8 + tig * 2;
            float v0 = acc[mi][ni][0];
            float v1 = acc[mi][ni][1];
            float v2 = acc[mi][ni][2];
            float v3 = acc[mi][ni][3];
            if (act) {
                v0 = feature_map(v0); v1 = feature_map(v1);
                v2 = feature_map(v2); v3 = feature_map(v3);
            }
            if (OUTK) {
                __half* C = (__half*)Cv;
                *(__half2*)&C[(size_t)r0 * DM + c0]       = __floats2half2_rn(v0, v1);
                *(__half2*)&C[(size_t)(r0 + 8) * DM + c0] = __floats2half2_rn(v2, v3);
            } else {
                float* C = (float*)Cv;
                *(float2*)&C[(size_t)r0 * DM + c0]       = make_float2(v0, v1);
                *(float2*)&C[(size_t)(r0 + 8) * DM + c0] = make_float2(v2, v3);
            }
        }
    }
}

// ---------------- kv_partial body (256 threads; compute on warps 0-3) --------
// smem overlay: [K0 8K][V0 8K][K1 8K][V1 8K] = 32KB inside dynamic region
__device__ __forceinline__
void kv_partial_body(const __half* __restrict__ Kp, const __half* __restrict__ Vp,
                     int s, int bh, char* sm)
{
    const int tid = threadIdx.x;
    const int w = tid >> 5;           // 0..7
    const int lane = tid & 31;
    const int gid = lane >> 2;
    const int tig = lane & 3;
    const int b = bh >> 4;
    const int h = bh & 15;

    const size_t rb = ((size_t)(b * L_SZ + s * (L_SZ / NSPLIT))) * DM + h * DK;
    const __half* Kg = Kp + rb;
    const __half* Vg = Vp + rb;

    const uint32_t base = su32(sm);
    const uint32_t ksb[2] = { base,         base + 16384 };
    const uint32_t vsb[2] = { base + 8192,  base + 24576 };

    auto load_chunk = [&](int buf, int n0) {
#pragma unroll
        for (int j = 0; j < 2; j++) {          // 512 chunks per matrix
            int i = tid + j * 256;
            int r = i >> 3, q = i & 7;
            CP16(ksb[buf] + SWZ(r * 128 + q * 16), Kg + (size_t)(n0 + r) * DM + q * 8);
            CP16(vsb[buf] + SWZ(r * 128 + q * 16), Vg + (size_t)(n0 + r) * DM + q * 8);
        }
        CP_COMMIT();
    };

    float accv[8][4];
#pragma unroll
    for (int ni = 0; ni < 8; ni++)
#pragma unroll
        for (int c = 0; c < 4; c++) accv[ni][c] = 0.0f;
    float accs[4] = {0, 0, 0, 0};

    const int trow = ((lane & 16) >> 1) + (lane & 7);
    const int tcol = (lane & 8) << 1;
    const uint32_t ONES2 = 0x3C003C00u;

    load_chunk(0, 0);

    for (int ch = 0; ch < 4; ch++) {
        const int cur = ch & 1;
        if (ch < 3) {
            load_chunk(cur ^ 1, (ch + 1) * 64);
            asm volatile("cp.async.wait_group 1;");
        } else {
            asm volatile("cp.async.wait_group 0;");
        }
        __syncthreads();

        if (w < 4) {
#pragma unroll
            for (int kk = 0; kk < 4; kk++) {
                uint32_t af[4];
                ldm_x4_t(af, ksb[cur] + SWZ((kk * 16 + trow) * 128 + w * 32 + tcol));
                uint32_t bf[4][4];
#pragma unroll
                for (int p = 0; p < 4; p++)
                    ldm_x4_t(bf[p], vsb[cur] + SWZ((kk * 16 + trow) * 128 + p * 32 + tcol));
#pragma unroll
                for (int p = 0; p < 4; p++) {
                    uint32_t b0[2] = { bf[p][0], bf[p][2] };
                    uint32_t b1[2] = { bf[p][1], bf[p][3] };
                    mma_f16(accv[2 * p + 0], af, b0);
                    mma_f16(accv[2 * p + 1], af, b1);
                }
                uint32_t bo[2] = { ONES2, ONES2 };
                mma_f16(accs, af, bo);
            }
        }
        __syncthreads();
    }

    if (w < 4) {
        float* outp = g_kv_part + ((size_t)(s * BH + bh)) * (DK * DK);
        const int r0 = w * 16 + gid;
#pragma unroll
        for (int ni = 0; ni < 8; ni++) {
            int c0 = ni * 8 + tig * 2;
            *(float2*)&outp[r0 * DK + c0]       = make_float2(accv[ni][0], accv[ni][1]);
            *(float2*)&outp[(r0 + 8) * DK + c0] = make_float2(accv[ni][2], accv[ni][3]);
        }
        if (tig == 0) {
            g_ks_part[(s * BH + bh) * DK + r0]     = accs[0];
            g_ks_part[(s * BH + bh) * DK + r0 + 8] = accs[2];
        }
    }
}

// ---------------- K/V projections (z: 0->K, 1->V) ----------------------------
__global__ __launch_bounds__(256, 2)
void gemm_kv(const __half* __restrict__ Ah, const __half* __restrict__ Wh,
             __half* __restrict__ Kp, __half* __restrict__ Vp)
{
    extern __shared__ __align__(16) char sm[];
    const int z = blockIdx.z;                       // 0 -> k, 1 -> v
    const __half* A = Ah + (size_t)(z + 1) * ROWS * DM;
    const __half* W = Wh + (size_t)(z + 1) * DM * DM;
    __half* C = (z == 0) ? Kp : Vp;
    gemm_core<1>(A, W, (void*)C, z == 0 ? 1 : 0,
                 blockIdx.y * GBM, blockIdx.x * GBN, sm);
}

// ---------------- fused: Q projection (blocks 0-511) + kv_partial (512-1023) -
__global__ __launch_bounds__(256, 2)
void fused_q_kvp(const __half* __restrict__ Ah, const __half* __restrict__ Wh,
                 __half* __restrict__ Qp,
                 const __half* __restrict__ Kp, const __half* __restrict__ Vp)
{
    extern __shared__ __align__(16) char sm[];
    const int b = blockIdx.x;
    if (b < 512) {
        gemm_core<1>(Ah, Wh, (void*)Qp, 1, (b >> 3) * GBM, (b & 7) * GBN, sm);
    } else {
        const int idx = b - 512;
        kv_partial_body(Kp, Vp, idx & (NSPLIT - 1), idx >> 3, sm);
    }
}

__global__ __launch_bounds__(256, 2)
void gemm_out(const __half* __restrict__ Mid, const __half* __restrict__ Wo,
              float* __restrict__ out)
{
    extern __shared__ __align__(16) char sm[];
    gemm_core<0>(Mid, Wo, (void*)out, 0, blockIdx.y * GBM, blockIdx.x * GBN, sm);
}

// ---------------- single fused fp32 -> fp16 convert --------------------------
__global__ __launch_bounds__(256)
void cvt_all(const float* __restrict__ q, const float* __restrict__ k,
             const float* __restrict__ v,
             const float* __restrict__ w0, const float* __restrict__ w1,
             const float* __restrict__ w2, const float* __restrict__ w3)
{
    const int b = blockIdx.x;
    const float* in;
    __half* out;
    int base;
    if (b < 1024) {
        const float* wsrc[4] = { w0, w1, w2, w3 };
        int w = b >> 8;
        in = wsrc[w];
        out = g_Wh[w];
        base = (b & 255) * 1024;
    } else {
        const float* asrc[3] = { q, k, v };
        int r = b - 1024;
        int z = r >> 11;
        in = asrc[z];
        out = g_Ah[z];
        base = (r & 2047) * 1024;
    }
#pragma unroll
    for (int j = 0; j < 4; j++) {
        int i = base + j * 256 + threadIdx.x;
        float4 x = ((const float4*)in)[i];
        ((__half2*)out)[2 * i]     = __floats2half2_rn(x.x, x.y);
        ((__half2*)out)[2 * i + 1] = __floats2half2_rn(x.z, x.w);
    }
}

// ---------------- kv combine -------------------------------------------------
__global__ __launch_bounds__(256)
void kv_combine_kernel()
{
    const int bh = blockIdx.x;
    const int qd = blockIdx.y;
    const int t = threadIdx.x;
    const int e4 = qd * 256 + t;
    float4 sum = {0, 0, 0, 0};
#pragma unroll
    for (int s = 0; s < NSPLIT; s++) {
        float4 p = ((const float4*)(g_kv_part + ((size_t)(s * BH + bh)) * (DK * DK)))[e4];
        sum.x += p.x; sum.y += p.y; sum.z += p.z; sum.w += p.w;
    }
    ((float4*)(g_KV + (size_t)bh * (DK * DK)))[e4] = sum;
    if (qd == 0 && t < DK) {
        float s2 = 0.0f;
#pragma unroll
        for (int s = 0; s < NSPLIT; s++)
            s2 += g_ks_part[(s * BH + bh) * DK + t];
        g_Ksum[bh * DK + t] = s2;
    }
}

// ---------------- attn_apply via tensor cores --------------------------------
__global__ __launch_bounds__(128)
void attn_apply_kernel(const __half* __restrict__ Qp, __half* __restrict__ Mid)
{
    __shared__ __align__(16) __half Qs[64 * 64];
    __shared__ __align__(16) __half KVh[64 * 64];
    __shared__ float Kss[DK];
    __shared__ float zp[128];
    __shared__ float zs[64];

    const int lc = blockIdx.x;
    const int bh = blockIdx.y;
    const int b = bh >> 4;
    const int h = bh & 15;
    const int tid = threadIdx.x;
    const int w = tid >> 5;
    const int lane = tid & 31;
    const int gid = lane >> 2;
    const int tig = lane & 3;

    const __half* Qg = Qp + ((size_t)(b * L_SZ + lc * 64)) * DM + h * DK;
    const uint32_t qsb = su32(Qs);
    const uint32_t kvb = su32(KVh);

#pragma unroll
    for (int j = 0; j < 4; j++) {
        int i = tid + j * 128;
        int r = i >> 3, q = i & 7;
        CP16(qsb + SWZ(r * 128 + q * 16), Qg + (size_t)r * DM + q * 8);
    }
    CP_COMMIT();

    const float* KVg = g_KV + (size_t)bh * (DK * DK);
#pragma unroll
    for (int j = 0; j < 16; j++) {
        int i = tid + j * 128;
        float2 p = ((const float2*)KVg)[i];
        int d = i >> 5, m = (i & 31) * 2;
        *(__half2*)((char*)KVh + SWZ(d * 128 + m * 2)) = __floats2half2_rn(p.x, p.y);
    }
    if (tid < DK) Kss[tid] = g_Ksum[bh * DK + tid];
    asm volatile("cp.async.wait_group 0;");
    __syncthreads();

    {
        const int r = tid & 63;
        const int hs = (tid >> 6) * 32;
        float p = 0.0f;
#pragma unroll
        for (int d = 0; d < 32; d++) {
            __half qv = *(const __half*)((const char*)Qs + SWZ(r * 128 + (hs + d) * 2));
            p += __half2float(qv) * Kss[hs + d];
        }
        zp[tid] = p;
    }
    __syncthreads();
    if (tid < 64) zs[tid] = 1.0f / (zp[tid] + zp[tid + 64] + EPS_Z);
    __syncthreads();

    float acc[8][4];
#pragma unroll
    for (int ni = 0; ni < 8; ni++)
#pragma unroll
        for (int c = 0; c < 4; c++) acc[ni][c] = 0.0f;

    const int lrow = lane & 15;
    const int lhi  = (lane >> 4) << 4;
    const int trow = ((lane & 16) >> 1) + (lane & 7);
    const int tcol = (lane & 8) << 1;

#pragma unroll
    for (int ks = 0; ks < 4; ks++) {
        uint32_t af[4];
        ldm_x4(af, qsb + SWZ((w * 16 + lrow) * 128 + ks * 32 + lhi));
        uint32_t bf[4][4];
#pragma unroll
        for (int p = 0; p < 4; p++)
            ldm_x4_t(bf[p], kvb + SWZ((ks * 16 + trow) * 128 + p * 32 + tcol));
#pragma unroll
        for (int p = 0; p < 4; p++) {
            uint32_t b0[2] = { bf[p][0], bf[p][2] };
            uint32_t b1[2] = { bf[p][1], bf[p][3] };
            mma_f16(acc[2 * p + 0], af, b0);
            mma_f16(acc[2 * p + 1], af, b1);
        }
    }

    const int r0 = w * 16 + gid;
    const float z0 = zs[r0];
    const float z1 = zs[r0 + 8];
    __half* Og = Mid + ((size_t)(b * L_SZ + lc * 64)) * DM + h * DK;
#pragma unroll
    for (int ni = 0; ni < 8; ni++) {
        int c0 = ni * 8 + tig * 2;
        *(__half2*)&Og[(size_t)r0 * DM + c0] =
            __floats2half2_rn(acc[ni][0] * z0, acc[ni][1] * z0);
        *(__half2*)&Og[(size_t)(r0 + 8) * DM + c0] =
            __floats2half2_rn(acc[ni][2] * z1, acc[ni][3] * z1);
    }
}

// ---------------- launch -----------------------------------------------------
extern "C" void kernel_launch(void* const* d_in, const int* in_sizes, int n_in,
                              void* d_out, int out_size)
{
    const float* q  = (const float*)d_in[0];
    const float* k  = (const float*)d_in[1];
    const float* v  = (const float*)d_in[2];
    const float* wq = (const float*)d_in[4];
    const float* wk = (const float*)d_in[5];
    const float* wv = (const float*)d_in[6];
    const float* wo = (const float*)d_in[7];
    float* out = (float*)d_out;

    __half *Wh, *Ah, *Qp, *Kp, *Vp, *Mid;
    cudaGetSymbolAddress((void**)&Wh,  g_Wh);
    cudaGetSymbolAddress((void**)&Ah,  g_Ah);
    cudaGetSymbolAddress((void**)&Qp,  g_Qp);
    cudaGetSymbolAddress((void**)&Kp,  g_Kp);
    cudaGetSymbolAddress((void**)&Vp,  g_Vp);
    cudaGetSymbolAddress((void**)&Mid, g_Mid);

    cudaFuncSetAttribute(gemm_kv,     cudaFuncAttributeMaxDynamicSharedMemorySize, GSMEM);
    cudaFuncSetAttribute(fused_q_kvp, cudaFuncAttributeMaxDynamicSharedMemorySize, GSMEM);
    cudaFuncSetAttribute(gemm_out,    cudaFuncAttributeMaxDynamicSharedMemorySize, GSMEM);

    cvt_all<<<1024 + 3 * 2048, 256>>>(q, k, v, wq, wk, wv, wo);

    dim3 gkv(DM / GBN, ROWS / GBM, 2);      // (8, 64, 2) = 1024 blocks -> K,V
    gemm_kv<<<gkv, 256, GSMEM>>>(Ah, Wh, Kp, Vp);

    fused_q_kvp<<<1024, 256, GSMEM>>>(Ah, Wh, Qp, Kp, Vp);

    kv_combine_kernel<<<dim3(BH, 4), 256>>>();
    attn_apply_kernel<<<dim3(L_SZ / 64, BH), 128>>>(Qp, Mid);

    dim3 gf(DM / GBN, ROWS / GBM);          // (8, 64) = 512 blocks
    gemm_out<<<gf, 256, GSMEM>>>(Mid, Wh + 3 * (size_t)DM * DM, out);
}

// round 13
// speedup vs baseline: 1.0061x; 1.0061x over previous
#include <cuda_runtime.h>
#include <cuda_fp16.h>
#include <cstdint>

#define B_SZ 4
#define L_SZ 2048
#define DM   1024
#define H_N  16
#define DK   64
#define BH   64
#define ROWS 8192
#define EPS_Z 1e-8f
#define NSPLIT 8

// ---------------- scratch ----------------------------------------------------
__device__ __half g_Wh[4][DM * DM];
__device__ __half g_Ah[3][ROWS * DM];
__device__ __half g_Qp[ROWS * DM];
__device__ __half g_Kp[ROWS * DM];
__device__ __half g_Vp[ROWS * DM];
__device__ __half g_Mid[ROWS * DM];
__device__ float  g_kv_part[NSPLIT * BH * DK * DK];
__device__ float  g_ks_part[NSPLIT * BH * DK];
__device__ float  g_KV[BH * DK * DK];
__device__ float  g_Ksum[BH * DK];
__device__ unsigned int g_kv_done;

// ---------------- helpers ----------------------------------------------------
__device__ __forceinline__ float feature_map(float x) {
    return x > 0.0f ? x + 1.0f : expf(x);
}
__device__ __forceinline__ uint32_t su32(const void* p) {
    uint32_t a;
    asm("{ .reg .u64 t; cvta.to.shared.u64 t, %1; cvt.u32.u64 %0, t; }" : "=r"(a) : "l"(p));
    return a;
}
#define CP16(s, g) asm volatile("cp.async.cg.shared.global [%0], [%1], 16;" :: "r"(s), "l"(g))
#define CP_COMMIT() asm volatile("cp.async.commit_group;")
#define SWZ(o) ((o) ^ (((o) >> 3) & 0x70))

__device__ __forceinline__ void ldm_x4(uint32_t* r, uint32_t addr) {
    asm volatile("ldmatrix.sync.aligned.m8n8.x4.shared.b16 {%0,%1,%2,%3}, [%4];"
                 : "=r"(r[0]), "=r"(r[1]), "=r"(r[2]), "=r"(r[3]) : "r"(addr));
}
__device__ __forceinline__ void ldm_x4_t(uint32_t* r, uint32_t addr) {
    asm volatile("ldmatrix.sync.aligned.m8n8.x4.trans.shared.b16 {%0,%1,%2,%3}, [%4];"
                 : "=r"(r[0]), "=r"(r[1]), "=r"(r[2]), "=r"(r[3]) : "r"(addr));
}
__device__ __forceinline__ void mma_f16(float* d, const uint32_t* a, const uint32_t* b) {
    asm volatile(
        "mma.sync.aligned.m16n8k16.row.col.f32.f16.f16.f32 "
        "{%0,%1,%2,%3},{%4,%5,%6,%7},{%8,%9},{%0,%1,%2,%3};\n"
        : "+f"(d[0]), "+f"(d[1]), "+f"(d[2]), "+f"(d[3])
        : "r"(a[0]), "r"(a[1]), "r"(a[2]), "r"(a[3]),
          "r"(b[0]), "r"(b[1]));
}

// ---------------- fp16 GEMM core (R11): BM=128 BN=128 BK=64, 256 thr ---------
#define GBM 128
#define GBN 128
#define ABYTES (GBM * 128)
#define BBYTES (GBN * 128)
#define STAGEB (ABYTES + BBYTES)  // 32768
#define GSMEM  (2 * STAGEB)       // 65536

template <int OUTK>
__device__ __forceinline__
void gemm_core(const __half* __restrict__ A, const __half* __restrict__ W,
               void* __restrict__ Cv, int act, int bm0, int bn0, char* sm)
{
    const int tid = threadIdx.x;
    const int wid = tid >> 5;
    const int lane = tid & 31;
    const int wm = wid >> 1;
    const int wn = wid & 1;
    const int gid = lane >> 2;
    const int tig = lane & 3;

    const __half* Ag = A + (size_t)bm0 * DM;
    const __half* Wg = W + (size_t)bn0 * DM;
    const uint32_t sbase = su32(sm);

    float acc[2][8][4];
#pragma unroll
    for (int mi = 0; mi < 2; mi++)
#pragma unroll
        for (int ni = 0; ni < 8; ni++)
#pragma unroll
            for (int c = 0; c < 4; c++) acc[mi][ni][c] = 0.0f;

    auto load_tile = [&](int stg, int k0) {
        const uint32_t ab = sbase + stg * STAGEB;
        const uint32_t bb = ab + ABYTES;
#pragma unroll
        for (int j = 0; j < 4; j++) {
            int i = tid + j * 256;
            int r = i >> 3, q = i & 7;
            CP16(ab + SWZ(r * 128 + q * 16), Ag + (size_t)r * DM + k0 + q * 8);
        }
#pragma unroll
        for (int j = 0; j < 4; j++) {
            int i = tid + j * 256;
            int r = i >> 3, q = i & 7;
            CP16(bb + SWZ(r * 128 + q * 16), Wg + (size_t)r * DM + k0 + q * 8);
        }
        CP_COMMIT();
    };

    const int KT = DM / 64;
    load_tile(0, 0);

    const int lrow = lane & 15;
    const int lhi  = (lane >> 4) << 4;

    for (int t = 0; t < KT; t++) {
        const int cur = t & 1;
        if (t + 1 < KT) {
            load_tile(cur ^ 1, (t + 1) * 64);
            asm volatile("cp.async.wait_group 1;");
        } else {
            asm volatile("cp.async.wait_group 0;");
        }
        __syncthreads();

        const uint32_t ab = sbase + cur * STAGEB;
        const uint32_t bb = ab + ABYTES;

#pragma unroll
        for (int ks = 0; ks < 4; ks++) {
            const int kboff = ks * 32 + lhi;
            uint32_t af[2][4];
            uint32_t bf[4][4];
#pragma unroll
            for (int mi = 0; mi < 2; mi++)
                ldm_x4(af[mi], ab + SWZ((wm * 32 + mi * 16 + lrow) * 128 + kboff));
#pragma unroll
            for (int p = 0; p < 4; p++)
                ldm_x4(bf[p], bb + SWZ((wn * 64 + p * 16 + lrow) * 128 + kboff));
#pragma unroll
            for (int mi = 0; mi < 2; mi++)
#pragma unroll
                for (int p = 0; p < 4; p++) {
                    uint32_t b0[2] = { bf[p][0], bf[p][2] };
                    uint32_t b1[2] = { bf[p][1], bf[p][3] };
                    mma_f16(acc[mi][2 * p + 0], af[mi], b0);
                    mma_f16(acc[mi][2 * p + 1], af[mi], b1);
                }
        }
        __syncthreads();
    }

#pragma unroll
    for (int mi = 0; mi < 2; mi++) {
        int r0 = bm0 + wm * 32 + mi * 16 + gid;
#pragma unroll
        for (int ni = 0; ni < 8; ni++) {
            int c0 = bn0 + wn * 64 + ni * 8 + tig * 2;
            float v0 = acc[mi][ni][0];
            float v1 = acc[mi][ni][1];
            float v2 = acc[mi][ni][2];
            float v3 = acc[mi][ni][3];
            if (act) {
                v0 = feature_map(v0); v1 = feature_map(v1);
                v2 = feature_map(v2); v3 = feature_map(v3);
            }
            if (OUTK) {
                __half* C = (__half*)Cv;
                *(__half2*)&C[(size_t)r0 * DM + c0]       = __floats2half2_rn(v0, v1);
                *(__half2*)&C[(size_t)(r0 + 8) * DM + c0] = __floats2half2_rn(v2, v3);
            } else {
                float* C = (float*)Cv;
                *(float2*)&C[(size_t)r0 * DM + c0]       = make_float2(v0, v1);
                *(float2*)&C[(size_t)(r0 + 8) * DM + c0] = make_float2(v2, v3);
            }
        }
    }
}

// ---------------- kv_partial body (256 threads; compute on warps 0-3) --------
__device__ __forceinline__
void kv_partial_body(const __half* __restrict__ Kp, const __half* __restrict__ Vp,
                     int s, int bh, char* sm)
{
    const int tid = threadIdx.x;
    const int w = tid >> 5;
    const int lane = tid & 31;
    const int gid = lane >> 2;
    const int tig = lane & 3;
    const int b = bh >> 4;
    const int h = bh & 15;

    const size_t rb = ((size_t)(b * L_SZ + s * (L_SZ / NSPLIT))) * DM + h * DK;
    const __half* Kg = Kp + rb;
    const __half* Vg = Vp + rb;

    const uint32_t base = su32(sm);
    const uint32_t ksb[2] = { base,         base + 16384 };
    const uint32_t vsb[2] = { base + 8192,  base + 24576 };

    auto load_chunk = [&](int buf, int n0) {
#pragma unroll
        for (int j = 0; j < 2; j++) {
            int i = tid + j * 256;
            int r = i >> 3, q = i & 7;
            CP16(ksb[buf] + SWZ(r * 128 + q * 16), Kg + (size_t)(n0 + r) * DM + q * 8);
            CP16(vsb[buf] + SWZ(r * 128 + q * 16), Vg + (size_t)(n0 + r) * DM + q * 8);
        }
        CP_COMMIT();
    };

    float accv[8][4];
#pragma unroll
    for (int ni = 0; ni < 8; ni++)
#pragma unroll
        for (int c = 0; c < 4; c++) accv[ni][c] = 0.0f;
    float accs[4] = {0, 0, 0, 0};

    const int trow = ((lane & 16) >> 1) + (lane & 7);
    const int tcol = (lane & 8) << 1;
    const uint32_t ONES2 = 0x3C003C00u;

    load_chunk(0, 0);

    for (int ch = 0; ch < 4; ch++) {
        const int cur = ch & 1;
        if (ch < 3) {
            load_chunk(cur ^ 1, (ch + 1) * 64);
            asm volatile("cp.async.wait_group 1;");
        } else {
            asm volatile("cp.async.wait_group 0;");
        }
        __syncthreads();

        if (w < 4) {
#pragma unroll
            for (int kk = 0; kk < 4; kk++) {
                uint32_t af[4];
                ldm_x4_t(af, ksb[cur] + SWZ((kk * 16 + trow) * 128 + w * 32 + tcol));
                uint32_t bf[4][4];
#pragma unroll
                for (int p = 0; p < 4; p++)
                    ldm_x4_t(bf[p], vsb[cur] + SWZ((kk * 16 + trow) * 128 + p * 32 + tcol));
#pragma unroll
                for (int p = 0; p < 4; p++) {
                    uint32_t b0[2] = { bf[p][0], bf[p][2] };
                    uint32_t b1[2] = { bf[p][1], bf[p][3] };
                    mma_f16(accv[2 * p + 0], af, b0);
                    mma_f16(accv[2 * p + 1], af, b1);
                }
                uint32_t bo[2] = { ONES2, ONES2 };
                mma_f16(accs, af, bo);
            }
        }
        __syncthreads();
    }

    if (w < 4) {
        float* outp = g_kv_part + ((size_t)(s * BH + bh)) * (DK * DK);
        const int r0 = w * 16 + gid;
#pragma unroll
        for (int ni = 0; ni < 8; ni++) {
            int c0 = ni * 8 + tig * 2;
            *(float2*)&outp[r0 * DK + c0]       = make_float2(accv[ni][0], accv[ni][1]);
            *(float2*)&outp[(r0 + 8) * DK + c0] = make_float2(accv[ni][2], accv[ni][3]);
        }
        if (tig == 0) {
            g_ks_part[(s * BH + bh) * DK + r0]     = accs[0];
            g_ks_part[(s * BH + bh) * DK + r0 + 8] = accs[2];
        }
    }
}

// ---------------- mega launch: K/V GEMMs + Q GEMM + kv_partial ---------------
// blocks 0-1023: K (0-511) and V (512-1023) projections; increment g_kv_done.
// blocks 1024-1535: Q projection.
// blocks 1536-2047: kv_partial; spin until g_kv_done == 1024.
__global__ __launch_bounds__(256, 2)
void mega_proj(const __half* __restrict__ Ah, const __half* __restrict__ Wh,
               __half* __restrict__ Qp, __half* __restrict__ Kp, __half* __restrict__ Vp)
{
    extern __shared__ __align__(16) char sm[];
    const int b = blockIdx.x;
    if (b < 1024) {
        const int z = b >> 9;                   // 0 -> K, 1 -> V
        const int bb = b & 511;
        const __half* A = Ah + (size_t)(z + 1) * ROWS * DM;
        const __half* W = Wh + (size_t)(z + 1) * DM * DM;
        __half* C = (z == 0) ? Kp : Vp;
        gemm_core<1>(A, W, (void*)C, z == 0 ? 1 : 0,
                     (bb >> 3) * GBM, (bb & 7) * GBN, sm);
        __threadfence();
        __syncthreads();
        if (threadIdx.x == 0) atomicAdd(&g_kv_done, 1u);
    } else if (b < 1536) {
        const int bb = b - 1024;
        gemm_core<1>(Ah, Wh, (void*)Qp, 1, (bb >> 3) * GBM, (bb & 7) * GBN, sm);
    } else {
        if (threadIdx.x == 0) {
            while (atomicAdd(&g_kv_done, 0u) < 1024u) { }
        }
        __syncthreads();
        const int idx = b - 1536;
        kv_partial_body(Kp, Vp, idx & (NSPLIT - 1), idx >> 3, sm);
    }
}

__global__ __launch_bounds__(256, 2)
void gemm_out(const __half* __restrict__ Mid, const __half* __restrict__ Wo,
              float* __restrict__ out)
{
    extern __shared__ __align__(16) char sm[];
    gemm_core<0>(Mid, Wo, (void*)out, 0, blockIdx.y * GBM, blockIdx.x * GBN, sm);
}

// ---------------- single fused fp32 -> fp16 convert (+ counter reset) --------
__global__ __launch_bounds__(256)
void cvt_all(const float* __restrict__ q, const float* __restrict__ k,
             const float* __restrict__ v,
             const float* __restrict__ w0, const float* __restrict__ w1,
             const float* __restrict__ w2, const float* __restrict__ w3)
{
    const int b = blockIdx.x;
    if (b == 0 && threadIdx.x == 0) g_kv_done = 0;
    const float* in;
    __half* out;
    int base;
    if (b < 1024) {
        const float* wsrc[4] = { w0, w1, w2, w3 };
        int w = b >> 8;
        in = wsrc[w];
        out = g_Wh[w];
        base = (b & 255) * 1024;
    } else {
        const float* asrc[3] = { q, k, v };
        int r = b - 1024;
        int z = r >> 11;
        in = asrc[z];
        out = g_Ah[z];
        base = (r & 2047) * 1024;
    }
#pragma unroll
    for (int j = 0; j < 4; j++) {
        int i = base + j * 256 + threadIdx.x;
        float4 x = ((const float4*)in)[i];
        ((__half2*)out)[2 * i]     = __floats2half2_rn(x.x, x.y);
        ((__half2*)out)[2 * i + 1] = __floats2half2_rn(x.z, x.w);
    }
}

// ---------------- kv combine -------------------------------------------------
__global__ __launch_bounds__(256)
void kv_combine_kernel()
{
    const int bh = blockIdx.x;
    const int qd = blockIdx.y;
    const int t = threadIdx.x;
    const int e4 = qd * 256 + t;
    float4 sum = {0, 0, 0, 0};
#pragma unroll
    for (int s = 0; s < NSPLIT; s++) {
        float4 p = ((const float4*)(g_kv_part + ((size_t)(s * BH + bh)) * (DK * DK)))[e4];
        sum.x += p.x; sum.y += p.y; sum.z += p.z; sum.w += p.w;
    }
    ((float4*)(g_KV + (size_t)bh * (DK * DK)))[e4] = sum;
    if (qd == 0 && t < DK) {
        float s2 = 0.0f;
#pragma unroll
        for (int s = 0; s < NSPLIT; s++)
            s2 += g_ks_part[(s * BH + bh) * DK + t];
        g_Ksum[bh * DK + t] = s2;
    }
}

// ---------------- attn_apply via tensor cores --------------------------------
__global__ __launch_bounds__(128)
void attn_apply_kernel(const __half* __restrict__ Qp, __half* __restrict__ Mid)
{
    __shared__ __align__(16) __half Qs[64 * 64];
    __shared__ __align__(16) __half KVh[64 * 64];
    __shared__ float Kss[DK];
    __shared__ float zp[128];
    __shared__ float zs[64];

    const int lc = blockIdx.x;
    const int bh = blockIdx.y;
    const int b = bh >> 4;
    const int h = bh & 15;
    const int tid = threadIdx.x;
    const int w = tid >> 5;
    const int lane = tid & 31;
    const int gid = lane >> 2;
    const int tig = lane & 3;

    const __half* Qg = Qp + ((size_t)(b * L_SZ + lc * 64)) * DM + h * DK;
    const uint32_t qsb = su32(Qs);
    const uint32_t kvb = su32(KVh);

#pragma unroll
    for (int j = 0; j < 4; j++) {
        int i = tid + j * 128;
        int r = i >> 3, q = i & 7;
        CP16(qsb + SWZ(r * 128 + q * 16), Qg + (size_t)r * DM + q * 8);
    }
    CP_COMMIT();

    const float* KVg = g_KV + (size_t)bh * (DK * DK);
#pragma unroll
    for (int j = 0; j < 16; j++) {
        int i = tid + j * 128;
        float2 p = ((const float2*)KVg)[i];
        int d = i >> 5, m = (i & 31) * 2;
        *(__half2*)((char*)KVh + SWZ(d * 128 + m * 2)) = __floats2half2_rn(p.x, p.y);
    }
    if (tid < DK) Kss[tid] = g_Ksum[bh * DK + tid];
    asm volatile("cp.async.wait_group 0;");
    __syncthreads();

    {
        const int r = tid & 63;
        const int hs = (tid >> 6) * 32;
        float p = 0.0f;
#pragma unroll
        for (int d = 0; d < 32; d++) {
            __half qv = *(const __half*)((const char*)Qs + SWZ(r * 128 + (hs + d) * 2));
            p += __half2float(qv) * Kss[hs + d];
        }
        zp[tid] = p;
    }
    __syncthreads();
    if (tid < 64) zs[tid] = 1.0f / (zp[tid] + zp[tid + 64] + EPS_Z);
    __syncthreads();

    float acc[8][4];
#pragma unroll
    for (int ni = 0; ni < 8; ni++)
#pragma unroll
        for (int c = 0; c < 4; c++) acc[ni][c] = 0.0f;

    const int lrow = lane & 15;
    const int lhi  = (lane >> 4) << 4;
    const int trow = ((lane & 16) >> 1) + (lane & 7);
    const int tcol = (lane & 8) << 1;

#pragma unroll
    for (int ks = 0; ks < 4; ks++) {
        uint32_t af[4];
        ldm_x4(af, qsb + SWZ((w * 16 + lrow) * 128 + ks * 32 + lhi));
        uint32_t bf[4][4];
#pragma unroll
        for (int p = 0; p < 4; p++)
            ldm_x4_t(bf[p], kvb + SWZ((ks * 16 + trow) * 128 + p * 32 + tcol));
#pragma unroll
        for (int p = 0; p < 4; p++) {
            uint32_t b0[2] = { bf[p][0], bf[p][2] };
            uint32_t b1[2] = { bf[p][1], bf[p][3] };
            mma_f16(acc[2 * p + 0], af, b0);
            mma_f16(acc[2 * p + 1], af, b1);
        }
    }

    const int r0 = w * 16 + gid;
    const float z0 = zs[r0];
    const float z1 = zs[r0 + 8];
    __half* Og = Mid + ((size_t)(b * L_SZ + lc * 64)) * DM + h * DK;
#pragma unroll
    for (int ni = 0; ni < 8; ni++) {
        int c0 = ni * 8 + tig * 2;
        *(__half2*)&Og[(size_t)r0 * DM + c0] =
            __floats2half2_rn(acc[ni][0] * z0, acc[ni][1] * z0);
        *(__half2*)&Og[(size_t)(r0 + 8) * DM + c0] =
            __floats2half2_rn(acc[ni][2] * z1, acc[ni][3] * z1);
    }
}

// ---------------- launch -----------------------------------------------------
extern "C" void kernel_launch(void* const* d_in, const int* in_sizes, int n_in,
                              void* d_out, int out_size)
{
    const float* q  = (const float*)d_in[0];
    const float* k  = (const float*)d_in[1];
    const float* v  = (const float*)d_in[2];
    const float* wq = (const float*)d_in[4];
    const float* wk = (const float*)d_in[5];
    const float* wv = (const float*)d_in[6];
    const float* wo = (const float*)d_in[7];
    float* out = (float*)d_out;

    __half *Wh, *Ah, *Qp, *Kp, *Vp, *Mid;
    cudaGetSymbolAddress((void**)&Wh,  g_Wh);
    cudaGetSymbolAddress((void**)&Ah,  g_Ah);
    cudaGetSymbolAddress((void**)&Qp,  g_Qp);
    cudaGetSymbolAddress((void**)&Kp,  g_Kp);
    cudaGetSymbolAddress((void**)&Vp,  g_Vp);
    cudaGetSymbolAddress((void**)&Mid, g_Mid);

    cudaFuncSetAttribute(mega_proj, cudaFuncAttributeMaxDynamicSharedMemorySize, GSMEM);
    cudaFuncSetAttribute(gemm_out,  cudaFuncAttributeMaxDynamicSharedMemorySize, GSMEM);

    cvt_all<<<1024 + 3 * 2048, 256>>>(q, k, v, wq, wk, wv, wo);

    mega_proj<<<2048, 256, GSMEM>>>(Ah, Wh, Qp, Kp, Vp);

    kv_combine_kernel<<<dim3(BH, 4), 256>>>();
    attn_apply_kernel<<<dim3(L_SZ / 64, BH), 128>>>(Qp, Mid);

    dim3 gf(DM / GBN, ROWS / GBM);          // (8, 64) = 512 blocks
    gemm_out<<<gf, 256, GSMEM>>>(Mid, Wh + 3 * (size_t)DM * DM, out);
}

// round 14
// speedup vs baseline: 1.0080x; 1.0018x over previous
#include <cuda_runtime.h>
#include <cuda_fp16.h>
#include <cstdint>

#define B_SZ 4
#define L_SZ 2048
#define DM   1024
#define H_N  16
#define DK   64
#define BH   64
#define ROWS 8192
#define EPS_Z 1e-8f
#define NSPLIT 8

// ---------------- scratch ----------------------------------------------------
__device__ __half g_Wh[4][DM * DM];
__device__ __half g_Ah[3][ROWS * DM];
__device__ __half g_Qp[ROWS * DM];
__device__ __half g_Kp[ROWS * DM];
__device__ __half g_Vp[ROWS * DM];
__device__ __half g_Mid[ROWS * DM];
__device__ float  g_kv_part[NSPLIT * BH * DK * DK];
__device__ float  g_ks_part[NSPLIT * BH * DK];
__device__ __half g_KVh[BH * DK * DK];     // fp16, pre-swizzled per head (8KB each)
__device__ float  g_Ksum[BH * DK];
__device__ unsigned int g_kv_done;

// ---------------- helpers ----------------------------------------------------
__device__ __forceinline__ float feature_map(float x) {
    return x > 0.0f ? x + 1.0f : expf(x);
}
__device__ __forceinline__ uint32_t su32(const void* p) {
    uint32_t a;
    asm("{ .reg .u64 t; cvta.to.shared.u64 t, %1; cvt.u32.u64 %0, t; }" : "=r"(a) : "l"(p));
    return a;
}
#define CP16(s, g) asm volatile("cp.async.cg.shared.global [%0], [%1], 16;" :: "r"(s), "l"(g))
#define CP_COMMIT() asm volatile("cp.async.commit_group;")
#define SWZ(o) ((o) ^ (((o) >> 3) & 0x70))

__device__ __forceinline__ void ldm_x4(uint32_t* r, uint32_t addr) {
    asm volatile("ldmatrix.sync.aligned.m8n8.x4.shared.b16 {%0,%1,%2,%3}, [%4];"
                 : "=r"(r[0]), "=r"(r[1]), "=r"(r[2]), "=r"(r[3]) : "r"(addr));
}
__device__ __forceinline__ void ldm_x4_t(uint32_t* r, uint32_t addr) {
    asm volatile("ldmatrix.sync.aligned.m8n8.x4.trans.shared.b16 {%0,%1,%2,%3}, [%4];"
                 : "=r"(r[0]), "=r"(r[1]), "=r"(r[2]), "=r"(r[3]) : "r"(addr));
}
__device__ __forceinline__ void mma_f16(float* d, const uint32_t* a, const uint32_t* b) {
    asm volatile(
        "mma.sync.aligned.m16n8k16.row.col.f32.f16.f16.f32 "
        "{%0,%1,%2,%3},{%4,%5,%6,%7},{%8,%9},{%0,%1,%2,%3};\n"
        : "+f"(d[0]), "+f"(d[1]), "+f"(d[2]), "+f"(d[3])
        : "r"(a[0]), "r"(a[1]), "r"(a[2]), "r"(a[3]),
          "r"(b[0]), "r"(b[1]));
}

// ---------------- fp16 GEMM core (R11): BM=128 BN=128 BK=64, 256 thr ---------
#define GBM 128
#define GBN 128
#define ABYTES (GBM * 128)
#define BBYTES (GBN * 128)
#define STAGEB (ABYTES + BBYTES)  // 32768
#define GSMEM  (2 * STAGEB)       // 65536

template <int OUTK>
__device__ __forceinline__
void gemm_core(const __half* __restrict__ A, const __half* __restrict__ W,
               void* __restrict__ Cv, int act, int bm0, int bn0, char* sm)
{
    const int tid = threadIdx.x;
    const int wid = tid >> 5;
    const int lane = tid & 31;
    const int wm = wid >> 1;
    const int wn = wid & 1;
    const int gid = lane >> 2;
    const int tig = lane & 3;

    const __half* Ag = A + (size_t)bm0 * DM;
    const __half* Wg = W + (size_t)bn0 * DM;
    const uint32_t sbase = su32(sm);

    float acc[2][8][4];
#pragma unroll
    for (int mi = 0; mi < 2; mi++)
#pragma unroll
        for (int ni = 0; ni < 8; ni++)
#pragma unroll
            for (int c = 0; c < 4; c++) acc[mi][ni][c] = 0.0f;

    auto load_tile = [&](int stg, int k0) {
        const uint32_t ab = sbase + stg * STAGEB;
        const uint32_t bb = ab + ABYTES;
#pragma unroll
        for (int j = 0; j < 4; j++) {
            int i = tid + j * 256;
            int r = i >> 3, q = i & 7;
            CP16(ab + SWZ(r * 128 + q * 16), Ag + (size_t)r * DM + k0 + q * 8);
        }
#pragma unroll
        for (int j = 0; j < 4; j++) {
            int i = tid + j * 256;
            int r = i >> 3, q = i & 7;
            CP16(bb + SWZ(r * 128 + q * 16), Wg + (size_t)r * DM + k0 + q * 8);
        }
        CP_COMMIT();
    };

    const int KT = DM / 64;
    load_tile(0, 0);

    const int lrow = lane & 15;
    const int lhi  = (lane >> 4) << 4;

    for (int t = 0; t < KT; t++) {
        const int cur = t & 1;
        if (t + 1 < KT) {
            load_tile(cur ^ 1, (t + 1) * 64);
            asm volatile("cp.async.wait_group 1;");
        } else {
            asm volatile("cp.async.wait_group 0;");
        }
        __syncthreads();

        const uint32_t ab = sbase + cur * STAGEB;
        const uint32_t bb = ab + ABYTES;

#pragma unroll
        for (int ks = 0; ks < 4; ks++) {
            const int kboff = ks * 32 + lhi;
            uint32_t af[2][4];
            uint32_t bf[4][4];
#pragma unroll
            for (int mi = 0; mi < 2; mi++)
                ldm_x4(af[mi], ab + SWZ((wm * 32 + mi * 16 + lrow) * 128 + kboff));
#pragma unroll
            for (int p = 0; p < 4; p++)
                ldm_x4(bf[p], bb + SWZ((wn * 64 + p * 16 + lrow) * 128 + kboff));
#pragma unroll
            for (int mi = 0; mi < 2; mi++)
#pragma unroll
                for (int p = 0; p < 4; p++) {
                    uint32_t b0[2] = { bf[p][0], bf[p][2] };
                    uint32_t b1[2] = { bf[p][1], bf[p][3] };
                    mma_f16(acc[mi][2 * p + 0], af[mi], b0);
                    mma_f16(acc[mi][2 * p + 1], af[mi], b1);
                }
        }
        __syncthreads();
    }

#pragma unroll
    for (int mi = 0; mi < 2; mi++) {
        int r0 = bm0 + wm * 32 + mi * 16 + gid;
#pragma unroll
        for (int ni = 0; ni < 8; ni++) {
            int c0 = bn0 + wn * 64 + ni * 8 + tig * 2;
            float v0 = acc[mi][ni][0];
            float v1 = acc[mi][ni][1];
            float v2 = acc[mi][ni][2];
            float v3 = acc[mi][ni][3];
            if (act) {
                v0 = feature_map(v0); v1 = feature_map(v1);
                v2 = feature_map(v2); v3 = feature_map(v3);
            }
            if (OUTK) {
                __half* C = (__half*)Cv;
                *(__half2*)&C[(size_t)r0 * DM + c0]       = __floats2half2_rn(v0, v1);
                *(__half2*)&C[(size_t)(r0 + 8) * DM + c0] = __floats2half2_rn(v2, v3);
            } else {
                float* C = (float*)Cv;
                *(float2*)&C[(size_t)r0 * DM + c0]       = make_float2(v0, v1);
                *(float2*)&C[(size_t)(r0 + 8) * DM + c0] = make_float2(v2, v3);
            }
        }
    }
}

// ---------------- kv_partial body (256 threads; compute on warps 0-3) --------
__device__ __forceinline__
void kv_partial_body(const __half* __restrict__ Kp, const __half* __restrict__ Vp,
                     int s, int bh, char* sm)
{
    const int tid = threadIdx.x;
    const int w = tid >> 5;
    const int lane = tid & 31;
    const int gid = lane >> 2;
    const int tig = lane & 3;
    const int b = bh >> 4;
    const int h = bh & 15;

    const size_t rb = ((size_t)(b * L_SZ + s * (L_SZ / NSPLIT))) * DM + h * DK;
    const __half* Kg = Kp + rb;
    const __half* Vg = Vp + rb;

    const uint32_t base = su32(sm);
    const uint32_t ksb[2] = { base,         base + 16384 };
    const uint32_t vsb[2] = { base + 8192,  base + 24576 };

    auto load_chunk = [&](int buf, int n0) {
#pragma unroll
        for (int j = 0; j < 2; j++) {
            int i = tid + j * 256;
            int r = i >> 3, q = i & 7;
            CP16(ksb[buf] + SWZ(r * 128 + q * 16), Kg + (size_t)(n0 + r) * DM + q * 8);
            CP16(vsb[buf] + SWZ(r * 128 + q * 16), Vg + (size_t)(n0 + r) * DM + q * 8);
        }
        CP_COMMIT();
    };

    float accv[8][4];
#pragma unroll
    for (int ni = 0; ni < 8; ni++)
#pragma unroll
        for (int c = 0; c < 4; c++) accv[ni][c] = 0.0f;
    float accs[4] = {0, 0, 0, 0};

    const int trow = ((lane & 16) >> 1) + (lane & 7);
    const int tcol = (lane & 8) << 1;
    const uint32_t ONES2 = 0x3C003C00u;

    load_chunk(0, 0);

    for (int ch = 0; ch < 4; ch++) {
        const int cur = ch & 1;
        if (ch < 3) {
            load_chunk(cur ^ 1, (ch + 1) * 64);
            asm volatile("cp.async.wait_group 1;");
        } else {
            asm volatile("cp.async.wait_group 0;");
        }
        __syncthreads();

        if (w < 4) {
#pragma unroll
            for (int kk = 0; kk < 4; kk++) {
                uint32_t af[4];
                ldm_x4_t(af, ksb[cur] + SWZ((kk * 16 + trow) * 128 + w * 32 + tcol));
                uint32_t bf[4][4];
#pragma unroll
                for (int p = 0; p < 4; p++)
                    ldm_x4_t(bf[p], vsb[cur] + SWZ((kk * 16 + trow) * 128 + p * 32 + tcol));
#pragma unroll
                for (int p = 0; p < 4; p++) {
                    uint32_t b0[2] = { bf[p][0], bf[p][2] };
                    uint32_t b1[2] = { bf[p][1], bf[p][3] };
                    mma_f16(accv[2 * p + 0], af, b0);
                    mma_f16(accv[2 * p + 1], af, b1);
                }
                uint32_t bo[2] = { ONES2, ONES2 };
                mma_f16(accs, af, bo);
            }
        }
        __syncthreads();
    }

    if (w < 4) {
        float* outp = g_kv_part + ((size_t)(s * BH + bh)) * (DK * DK);
        const int r0 = w * 16 + gid;
#pragma unroll
        for (int ni = 0; ni < 8; ni++) {
            int c0 = ni * 8 + tig * 2;
            *(float2*)&outp[r0 * DK + c0]       = make_float2(accv[ni][0], accv[ni][1]);
            *(float2*)&outp[(r0 + 8) * DK + c0] = make_float2(accv[ni][2], accv[ni][3]);
        }
        if (tig == 0) {
            g_ks_part[(s * BH + bh) * DK + r0]     = accs[0];
            g_ks_part[(s * BH + bh) * DK + r0 + 8] = accs[2];
        }
    }
}

// ---------------- mega launch: K/V GEMMs + Q GEMM + kv_partial ---------------
__global__ __launch_bounds__(256, 2)
void mega_proj(const __half* __restrict__ Ah, const __half* __restrict__ Wh,
               __half* __restrict__ Qp, __half* __restrict__ Kp, __half* __restrict__ Vp)
{
    extern __shared__ __align__(16) char sm[];
    const int b = blockIdx.x;
    if (b < 1024) {
        const int z = b >> 9;                   // 0 -> K, 1 -> V
        const int bb = b & 511;
        const __half* A = Ah + (size_t)(z + 1) * ROWS * DM;
        const __half* W = Wh + (size_t)(z + 1) * DM * DM;
        __half* C = (z == 0) ? Kp : Vp;
        gemm_core<1>(A, W, (void*)C, z == 0 ? 1 : 0,
                     (bb >> 3) * GBM, (bb & 7) * GBN, sm);
        __threadfence();
        __syncthreads();
        if (threadIdx.x == 0) atomicAdd(&g_kv_done, 1u);
    } else if (b < 1536) {
        const int bb = b - 1024;
        gemm_core<1>(Ah, Wh, (void*)Qp, 1, (bb >> 3) * GBM, (bb & 7) * GBN, sm);
    } else {
        if (threadIdx.x == 0) {
            while (atomicAdd(&g_kv_done, 0u) < 1024u) { }
        }
        __syncthreads();
        const int idx = b - 1536;
        kv_partial_body(Kp, Vp, idx & (NSPLIT - 1), idx >> 3, sm);
    }
}

__global__ __launch_bounds__(256, 2)
void gemm_out(const __half* __restrict__ Mid, const __half* __restrict__ Wo,
              float* __restrict__ out)
{
    extern __shared__ __align__(16) char sm[];
    gemm_core<0>(Mid, Wo, (void*)out, 0, blockIdx.y * GBM, blockIdx.x * GBN, sm);
}

// ---------------- single fused fp32 -> fp16 convert (+ counter reset) --------
__global__ __launch_bounds__(256)
void cvt_all(const float* __restrict__ q, const float* __restrict__ k,
             const float* __restrict__ v,
             const float* __restrict__ w0, const float* __restrict__ w1,
             const float* __restrict__ w2, const float* __restrict__ w3)
{
    const int b = blockIdx.x;
    if (b == 0 && threadIdx.x == 0) g_kv_done = 0;
    const float* in;
    __half* out;
    int base;
    if (b < 1024) {
        const float* wsrc[4] = { w0, w1, w2, w3 };
        int w = b >> 8;
        in = wsrc[w];
        out = g_Wh[w];
        base = (b & 255) * 1024;
    } else {
        const float* asrc[3] = { q, k, v };
        int r = b - 1024;
        int z = r >> 11;
        in = asrc[z];
        out = g_Ah[z];
        base = (r & 2047) * 1024;
    }
#pragma unroll
    for (int j = 0; j < 4; j++) {
        int i = base + j * 256 + threadIdx.x;
        float4 x = ((const float4*)in)[i];
        ((__half2*)out)[2 * i]     = __floats2half2_rn(x.x, x.y);
        ((__half2*)out)[2 * i + 1] = __floats2half2_rn(x.z, x.w);
    }
}

// ---------------- kv combine: sum partials -> fp16 pre-swizzled KV -----------
// grid (BH, 4), 256 thr. Thread handles one float4 (row d, 4 m-values).
__global__ __launch_bounds__(256)
void kv_combine_kernel()
{
    const int bh = blockIdx.x;
    const int qd = blockIdx.y;
    const int t = threadIdx.x;
    const int e4 = qd * 256 + t;                 // 0..1023
    float4 sum = {0, 0, 0, 0};
#pragma unroll
    for (int s = 0; s < NSPLIT; s++) {
        float4 p = ((const float4*)(g_kv_part + ((size_t)(s * BH + bh)) * (DK * DK)))[e4];
        sum.x += p.x; sum.y += p.y; sum.z += p.z; sum.w += p.w;
    }
    // element (d, m0..m0+3), d = e4>>4, m0 = (e4&15)*4; byte off within 8KB tile
    const int d = e4 >> 4;
    const int boff = d * 128 + (e4 & 15) * 8;    // 8-byte aligned
    uint2 hv;
    __half2 h0 = __floats2half2_rn(sum.x, sum.y);
    __half2 h1 = __floats2half2_rn(sum.z, sum.w);
    hv.x = *(uint32_t*)&h0;
    hv.y = *(uint32_t*)&h1;
    *(uint2*)((char*)(g_KVh + (size_t)bh * (DK * DK)) + SWZ(boff)) = hv;

    if (qd == 0 && t < DK) {
        float s2 = 0.0f;
#pragma unroll
        for (int s = 0; s < NSPLIT; s++)
            s2 += g_ks_part[(s * BH + bh) * DK + t];
        g_Ksum[bh * DK + t] = s2;
    }
}

// ---------------- attn_apply: 128 rows/block, pre-swizzled KV ----------------
// grid (L/128 = 16, BH), 256 threads (8 warps, 16 rows each).
__global__ __launch_bounds__(256)
void attn_apply_kernel(const __half* __restrict__ Qp, __half* __restrict__ Mid)
{
    __shared__ __align__(16) __half Qs[128 * 64];
    __shared__ __align__(16) __half KVh[64 * 64];
    __shared__ float Kss[DK];
    __shared__ float zp[256];
    __shared__ float zs[128];

    const int lc = blockIdx.x;
    const int bh = blockIdx.y;
    const int b = bh >> 4;
    const int h = bh & 15;
    const int tid = threadIdx.x;
    const int w = tid >> 5;
    const int lane = tid & 31;
    const int gid = lane >> 2;
    const int tig = lane & 3;

    const __half* Qg = Qp + ((size_t)(b * L_SZ + lc * 128)) * DM + h * DK;
    const uint32_t qsb = su32(Qs);
    const uint32_t kvb = su32(KVh);

    // Q tile: 128 rows x 128B swizzled
#pragma unroll
    for (int j = 0; j < 4; j++) {
        int i = tid + j * 256;
        int r = i >> 3, q = i & 7;
        CP16(qsb + SWZ(r * 128 + q * 16), Qg + (size_t)r * DM + q * 8);
    }
    // KV tile: straight 8KB copy (already swizzled in global)
    {
        const char* KVg = (const char*)(g_KVh + (size_t)bh * (DK * DK));
#pragma unroll
        for (int j = 0; j < 2; j++) {
            int i = tid + j * 256;
            CP16(kvb + i * 16, KVg + i * 16);
        }
    }
    CP_COMMIT();
    if (tid < DK) Kss[tid] = g_Ksum[bh * DK + tid];
    asm volatile("cp.async.wait_group 0;");
    __syncthreads();

    // z: two threads per row (256 thr, 128 rows)
    {
        const int r = tid & 127;
        const int hs = (tid >> 7) * 32;
        float p = 0.0f;
#pragma unroll
        for (int d = 0; d < 32; d++) {
            __half qv = *(const __half*)((const char*)Qs + SWZ(r * 128 + (hs + d) * 2));
            p += __half2float(qv) * Kss[hs + d];
        }
        zp[tid] = p;
    }
    __syncthreads();
    if (tid < 128) zs[tid] = 1.0f / (zp[tid] + zp[tid + 128] + EPS_Z);
    __syncthreads();

    float acc[8][4];
#pragma unroll
    for (int ni = 0; ni < 8; ni++)
#pragma unroll
        for (int c = 0; c < 4; c++) acc[ni][c] = 0.0f;

    const int lrow = lane & 15;
    const int lhi  = (lane >> 4) << 4;
    const int trow = ((lane & 16) >> 1) + (lane & 7);
    const int tcol = (lane & 8) << 1;

#pragma unroll
    for (int ks = 0; ks < 4; ks++) {
        uint32_t af[4];
        ldm_x4(af, qsb + SWZ((w * 16 + lrow) * 128 + ks * 32 + lhi));
        uint32_t bf[4][4];
#pragma unroll
        for (int p = 0; p < 4; p++)
            ldm_x4_t(bf[p], kvb + SWZ((ks * 16 + trow) * 128 + p * 32 + tcol));
#pragma unroll
        for (int p = 0; p < 4; p++) {
            uint32_t b0[2] = { bf[p][0], bf[p][2] };
            uint32_t b1[2] = { bf[p][1], bf[p][3] };
            mma_f16(acc[2 * p + 0], af, b0);
            mma_f16(acc[2 * p + 1], af, b1);
        }
    }

    const int r0 = w * 16 + gid;               // 0..127
    const float z0 = zs[r0];
    const float z1 = zs[r0 + 8];
    __half* Og = Mid + ((size_t)(b * L_SZ + lc * 128)) * DM + h * DK;
#pragma unroll
    for (int ni = 0; ni < 8; ni++) {
        int c0 = ni * 8 + tig * 2;
        *(__half2*)&Og[(size_t)r0 * DM + c0] =
            __floats2half2_rn(acc[ni][0] * z0, acc[ni][1] * z0);
        *(__half2*)&Og[(size_t)(r0 + 8) * DM + c0] =
            __floats2half2_rn(acc[ni][2] * z1, acc[ni][3] * z1);
    }
}

// ---------------- launch -----------------------------------------------------
extern "C" void kernel_launch(void* const* d_in, const int* in_sizes, int n_in,
                              void* d_out, int out_size)
{
    const float* q  = (const float*)d_in[0];
    const float* k  = (const float*)d_in[1];
    const float* v  = (const float*)d_in[2];
    const float* wq = (const float*)d_in[4];
    const float* wk = (const float*)d_in[5];
    const float* wv = (const float*)d_in[6];
    const float* wo = (const float*)d_in[7];
    float* out = (float*)d_out;

    __half *Wh, *Ah, *Qp, *Kp, *Vp, *Mid;
    cudaGetSymbolAddress((void**)&Wh,  g_Wh);
    cudaGetSymbolAddress((void**)&Ah,  g_Ah);
    cudaGetSymbolAddress((void**)&Qp,  g_Qp);
    cudaGetSymbolAddress((void**)&Kp,  g_Kp);
    cudaGetSymbolAddress((void**)&Vp,  g_Vp);
    cudaGetSymbolAddress((void**)&Mid, g_Mid);

    cudaFuncSetAttribute(mega_proj, cudaFuncAttributeMaxDynamicSharedMemorySize, GSMEM);
    cudaFuncSetAttribute(gemm_out,  cudaFuncAttributeMaxDynamicSharedMemorySize, GSMEM);

    cvt_all<<<1024 + 3 * 2048, 256>>>(q, k, v, wq, wk, wv, wo);

    mega_proj<<<2048, 256, GSMEM>>>(Ah, Wh, Qp, Kp, Vp);

    kv_combine_kernel<<<dim3(BH, 4), 256>>>();
    attn_apply_kernel<<<dim3(L_SZ / 128, BH), 256>>>(Qp, Mid);

    dim3 gf(DM / GBN, ROWS / GBM);          // (8, 64) = 512 blocks
    gemm_out<<<gf, 256, GSMEM>>>(Mid, Wh + 3 * (size_t)DM * DM, out);
}

// round 15
// speedup vs baseline: 1.0170x; 1.0089x over previous
#include <cuda_runtime.h>
#include <cuda_fp16.h>
#include <cstdint>

#define B_SZ 4
#define L_SZ 2048
#define DM   1024
#define H_N  16
#define DK   64
#define BH   64
#define ROWS 8192
#define EPS_Z 1e-8f
#define NSPLIT 8

// ---------------- scratch ----------------------------------------------------
__device__ __half g_Wh[4][DM * DM];
__device__ __half g_Ah[3][ROWS * DM];
__device__ __half g_Qp[ROWS * DM];
__device__ __half g_Kp[ROWS * DM];
__device__ __half g_Vp[ROWS * DM];
__device__ __half g_Mid[ROWS * DM];
__device__ float  g_kv_part[NSPLIT * BH * DK * DK];
__device__ float  g_ks_part[NSPLIT * BH * DK];
__device__ __half g_KVh[BH * DK * DK];     // fp16, pre-swizzled per head (8KB each)
__device__ float  g_Ksum[BH * DK];
__device__ unsigned int g_kv_done;

// ---------------- helpers ----------------------------------------------------
__device__ __forceinline__ float feature_map(float x) {
    return x > 0.0f ? x + 1.0f : expf(x);
}
__device__ __forceinline__ uint32_t su32(const void* p) {
    uint32_t a;
    asm("{ .reg .u64 t; cvta.to.shared.u64 t, %1; cvt.u32.u64 %0, t; }" : "=r"(a) : "l"(p));
    return a;
}
#define CP16(s, g) asm volatile("cp.async.cg.shared.global [%0], [%1], 16;" :: "r"(s), "l"(g))
#define CP_COMMIT() asm volatile("cp.async.commit_group;")
#define SWZ(o) ((o) ^ (((o) >> 3) & 0x70))

__device__ __forceinline__ void ldm_x4(uint32_t* r, uint32_t addr) {
    asm volatile("ldmatrix.sync.aligned.m8n8.x4.shared.b16 {%0,%1,%2,%3}, [%4];"
                 : "=r"(r[0]), "=r"(r[1]), "=r"(r[2]), "=r"(r[3]) : "r"(addr));
}
__device__ __forceinline__ void ldm_x4_t(uint32_t* r, uint32_t addr) {
    asm volatile("ldmatrix.sync.aligned.m8n8.x4.trans.shared.b16 {%0,%1,%2,%3}, [%4];"
                 : "=r"(r[0]), "=r"(r[1]), "=r"(r[2]), "=r"(r[3]) : "r"(addr));
}
__device__ __forceinline__ void mma_f16(float* d, const uint32_t* a, const uint32_t* b) {
    asm volatile(
        "mma.sync.aligned.m16n8k16.row.col.f32.f16.f16.f32 "
        "{%0,%1,%2,%3},{%4,%5,%6,%7},{%8,%9},{%0,%1,%2,%3};\n"
        : "+f"(d[0]), "+f"(d[1]), "+f"(d[2]), "+f"(d[3])
        : "r"(a[0]), "r"(a[1]), "r"(a[2]), "r"(a[3]),
          "r"(b[0]), "r"(b[1]));
}

// ---------------- fp16 GEMM core (R11): BM=128 BN=128 BK=64, 256 thr ---------
#define GBM 128
#define GBN 128
#define ABYTES (GBM * 128)
#define BBYTES (GBN * 128)
#define STAGEB (ABYTES + BBYTES)  // 32768
#define GSMEM  (2 * STAGEB)       // 65536

template <int OUTK>
__device__ __forceinline__
void gemm_core(const __half* __restrict__ A, const __half* __restrict__ W,
               void* __restrict__ Cv, int act, int bm0, int bn0, char* sm)
{
    const int tid = threadIdx.x;
    const int wid = tid >> 5;
    const int lane = tid & 31;
    const int wm = wid >> 1;
    const int wn = wid & 1;
    const int gid = lane >> 2;
    const int tig = lane & 3;

    const __half* Ag = A + (size_t)bm0 * DM;
    const __half* Wg = W + (size_t)bn0 * DM;
    const uint32_t sbase = su32(sm);

    float acc[2][8][4];
#pragma unroll
    for (int mi = 0; mi < 2; mi++)
#pragma unroll
        for (int ni = 0; ni < 8; ni++)
#pragma unroll
            for (int c = 0; c < 4; c++) acc[mi][ni][c] = 0.0f;

    auto load_tile = [&](int stg, int k0) {
        const uint32_t ab = sbase + stg * STAGEB;
        const uint32_t bb = ab + ABYTES;
#pragma unroll
        for (int j = 0; j < 4; j++) {
            int i = tid + j * 256;
            int r = i >> 3, q = i & 7;
            CP16(ab + SWZ(r * 128 + q * 16), Ag + (size_t)r * DM + k0 + q * 8);
        }
#pragma unroll
        for (int j = 0; j < 4; j++) {
            int i = tid + j * 256;
            int r = i >> 3, q = i & 7;
            CP16(bb + SWZ(r * 128 + q * 16), Wg + (size_t)r * DM + k0 + q * 8);
        }
        CP_COMMIT();
    };

    const int KT = DM / 64;
    load_tile(0, 0);

    const int lrow = lane & 15;
    const int lhi  = (lane >> 4) << 4;

    for (int t = 0; t < KT; t++) {
        const int cur = t & 1;
        if (t + 1 < KT) {
            load_tile(cur ^ 1, (t + 1) * 64);
            asm volatile("cp.async.wait_group 1;");
        } else {
            asm volatile("cp.async.wait_group 0;");
        }
        __syncthreads();

        const uint32_t ab = sbase + cur * STAGEB;
        const uint32_t bb = ab + ABYTES;

#pragma unroll
        for (int ks = 0; ks < 4; ks++) {
            const int kboff = ks * 32 + lhi;
            uint32_t af[2][4];
            uint32_t bf[4][4];
#pragma unroll
            for (int mi = 0; mi < 2; mi++)
                ldm_x4(af[mi], ab + SWZ((wm * 32 + mi * 16 + lrow) * 128 + kboff));
#pragma unroll
            for (int p = 0; p < 4; p++)
                ldm_x4(bf[p], bb + SWZ((wn * 64 + p * 16 + lrow) * 128 + kboff));
#pragma unroll
            for (int mi = 0; mi < 2; mi++)
#pragma unroll
                for (int p = 0; p < 4; p++) {
                    uint32_t b0[2] = { bf[p][0], bf[p][2] };
                    uint32_t b1[2] = { bf[p][1], bf[p][3] };
                    mma_f16(acc[mi][2 * p + 0], af[mi], b0);
                    mma_f16(acc[mi][2 * p + 1], af[mi], b1);
                }
        }
        __syncthreads();
    }

#pragma unroll
    for (int mi = 0; mi < 2; mi++) {
        int r0 = bm0 + wm * 32 + mi * 16 + gid;
#pragma unroll
        for (int ni = 0; ni < 8; ni++) {
            int c0 = bn0 + wn * 64 + ni * 8 + tig * 2;
            float v0 = acc[mi][ni][0];
            float v1 = acc[mi][ni][1];
            float v2 = acc[mi][ni][2];
            float v3 = acc[mi][ni][3];
            if (act) {
                v0 = feature_map(v0); v1 = feature_map(v1);
                v2 = feature_map(v2); v3 = feature_map(v3);
            }
            if (OUTK) {
                __half* C = (__half*)Cv;
                *(__half2*)&C[(size_t)r0 * DM + c0]       = __floats2half2_rn(v0, v1);
                *(__half2*)&C[(size_t)(r0 + 8) * DM + c0] = __floats2half2_rn(v2, v3);
            } else {
                float* C = (float*)Cv;
                *(float2*)&C[(size_t)r0 * DM + c0]       = make_float2(v0, v1);
                *(float2*)&C[(size_t)(r0 + 8) * DM + c0] = make_float2(v2, v3);
            }
        }
    }
}

// ---------------- kv_partial body (256 threads; compute on warps 0-3) --------
__device__ __forceinline__
void kv_partial_body(const __half* __restrict__ Kp, const __half* __restrict__ Vp,
                     int s, int bh, char* sm)
{
    const int tid = threadIdx.x;
    const int w = tid >> 5;
    const int lane = tid & 31;
    const int gid = lane >> 2;
    const int tig = lane & 3;
    const int b = bh >> 4;
    const int h = bh & 15;

    const size_t rb = ((size_t)(b * L_SZ + s * (L_SZ / NSPLIT))) * DM + h * DK;
    const __half* Kg = Kp + rb;
    const __half* Vg = Vp + rb;

    const uint32_t base = su32(sm);
    const uint32_t ksb[2] = { base,         base + 16384 };
    const uint32_t vsb[2] = { base + 8192,  base + 24576 };

    auto load_chunk = [&](int buf, int n0) {
#pragma unroll
        for (int j = 0; j < 2; j++) {
            int i = tid + j * 256;
            int r = i >> 3, q = i & 7;
            CP16(ksb[buf] + SWZ(r * 128 + q * 16), Kg + (size_t)(n0 + r) * DM + q * 8);
            CP16(vsb[buf] + SWZ(r * 128 + q * 16), Vg + (size_t)(n0 + r) * DM + q * 8);
        }
        CP_COMMIT();
    };

    float accv[8][4];
#pragma unroll
    for (int ni = 0; ni < 8; ni++)
#pragma unroll
        for (int c = 0; c < 4; c++) accv[ni][c] = 0.0f;
    float accs[4] = {0, 0, 0, 0};

    const int trow = ((lane & 16) >> 1) + (lane & 7);
    const int tcol = (lane & 8) << 1;
    const uint32_t ONES2 = 0x3C003C00u;

    load_chunk(0, 0);

    for (int ch = 0; ch < 4; ch++) {
        const int cur = ch & 1;
        if (ch < 3) {
            load_chunk(cur ^ 1, (ch + 1) * 64);
            asm volatile("cp.async.wait_group 1;");
        } else {
            asm volatile("cp.async.wait_group 0;");
        }
        __syncthreads();

        if (w < 4) {
#pragma unroll
            for (int kk = 0; kk < 4; kk++) {
                uint32_t af[4];
                ldm_x4_t(af, ksb[cur] + SWZ((kk * 16 + trow) * 128 + w * 32 + tcol));
                uint32_t bf[4][4];
#pragma unroll
                for (int p = 0; p < 4; p++)
                    ldm_x4_t(bf[p], vsb[cur] + SWZ((kk * 16 + trow) * 128 + p * 32 + tcol));
#pragma unroll
                for (int p = 0; p < 4; p++) {
                    uint32_t b0[2] = { bf[p][0], bf[p][2] };
                    uint32_t b1[2] = { bf[p][1], bf[p][3] };
                    mma_f16(accv[2 * p + 0], af, b0);
                    mma_f16(accv[2 * p + 1], af, b1);
                }
                uint32_t bo[2] = { ONES2, ONES2 };
                mma_f16(accs, af, bo);
            }
        }
        __syncthreads();
    }

    if (w < 4) {
        float* outp = g_kv_part + ((size_t)(s * BH + bh)) * (DK * DK);
        const int r0 = w * 16 + gid;
#pragma unroll
        for (int ni = 0; ni < 8; ni++) {
            int c0 = ni * 8 + tig * 2;
            *(float2*)&outp[r0 * DK + c0]       = make_float2(accv[ni][0], accv[ni][1]);
            *(float2*)&outp[(r0 + 8) * DK + c0] = make_float2(accv[ni][2], accv[ni][3]);
        }
        if (tig == 0) {
            g_ks_part[(s * BH + bh) * DK + r0]     = accs[0];
            g_ks_part[(s * BH + bh) * DK + r0 + 8] = accs[2];
        }
    }
}

// ---------------- mega launch: K/V GEMMs + Q GEMM + kv_partial ---------------
__global__ __launch_bounds__(256, 2)
void mega_proj(const __half* __restrict__ Ah, const __half* __restrict__ Wh,
               __half* __restrict__ Qp, __half* __restrict__ Kp, __half* __restrict__ Vp)
{
    extern __shared__ __align__(16) char sm[];
    const int b = blockIdx.x;
    if (b < 1024) {
        const int z = b >> 9;                   // 0 -> K, 1 -> V
        const int bb = b & 511;
        const __half* A = Ah + (size_t)(z + 1) * ROWS * DM;
        const __half* W = Wh + (size_t)(z + 1) * DM * DM;
        __half* C = (z == 0) ? Kp : Vp;
        gemm_core<1>(A, W, (void*)C, z == 0 ? 1 : 0,
                     (bb >> 3) * GBM, (bb & 7) * GBN, sm);
        __threadfence();
        __syncthreads();
        if (threadIdx.x == 0) atomicAdd(&g_kv_done, 1u);
    } else if (b < 1536) {
        const int bb = b - 1024;
        gemm_core<1>(Ah, Wh, (void*)Qp, 1, (bb >> 3) * GBM, (bb & 7) * GBN, sm);
    } else {
        if (threadIdx.x == 0) {
            while (atomicAdd(&g_kv_done, 0u) < 1024u) { }
        }
        __syncthreads();
        const int idx = b - 1536;
        kv_partial_body(Kp, Vp, idx & (NSPLIT - 1), idx >> 3, sm);
    }
}

__global__ __launch_bounds__(256, 2)
void gemm_out(const __half* __restrict__ Mid, const __half* __restrict__ Wo,
              float* __restrict__ out)
{
    extern __shared__ __align__(16) char sm[];
    gemm_core<0>(Mid, Wo, (void*)out, 0, blockIdx.y * GBM, blockIdx.x * GBN, sm);
}

// ---------------- single fused fp32 -> fp16 convert (8 float4 / thread) ------
// weights: 4 x 128 blocks; inputs: 3 x 1024 blocks. total 3584.
__global__ __launch_bounds__(256)
void cvt_all(const float* __restrict__ q, const float* __restrict__ k,
             const float* __restrict__ v,
             const float* __restrict__ w0, const float* __restrict__ w1,
             const float* __restrict__ w2, const float* __restrict__ w3)
{
    const int b = blockIdx.x;
    if (b == 0 && threadIdx.x == 0) g_kv_done = 0;
    const float* in;
    __half* out;
    int base;
    if (b < 512) {
        const float* wsrc[4] = { w0, w1, w2, w3 };
        int w = b >> 7;
        in = wsrc[w];
        out = g_Wh[w];
        base = (b & 127) * 2048;
    } else {
        const float* asrc[3] = { q, k, v };
        int r = b - 512;
        int z = r >> 10;
        in = asrc[z];
        out = g_Ah[z];
        base = (r & 1023) * 2048;
    }
#pragma unroll
    for (int j = 0; j < 8; j++) {
        int i = base + j * 256 + threadIdx.x;
        float4 x = ((const float4*)in)[i];
        ((__half2*)out)[2 * i]     = __floats2half2_rn(x.x, x.y);
        ((__half2*)out)[2 * i + 1] = __floats2half2_rn(x.z, x.w);
    }
}

// ---------------- kv combine: sum partials -> fp16 pre-swizzled KV -----------
__global__ __launch_bounds__(256)
void kv_combine_kernel()
{
    const int bh = blockIdx.x;
    const int qd = blockIdx.y;
    const int t = threadIdx.x;
    const int e4 = qd * 256 + t;                 // 0..1023
    float4 sum = {0, 0, 0, 0};
#pragma unroll
    for (int s = 0; s < NSPLIT; s++) {
        float4 p = ((const float4*)(g_kv_part + ((size_t)(s * BH + bh)) * (DK * DK)))[e4];
        sum.x += p.x; sum.y += p.y; sum.z += p.z; sum.w += p.w;
    }
    const int d = e4 >> 4;
    const int boff = d * 128 + (e4 & 15) * 8;
    uint2 hv;
    __half2 h0 = __floats2half2_rn(sum.x, sum.y);
    __half2 h1 = __floats2half2_rn(sum.z, sum.w);
    hv.x = *(uint32_t*)&h0;
    hv.y = *(uint32_t*)&h1;
    *(uint2*)((char*)(g_KVh + (size_t)bh * (DK * DK)) + SWZ(boff)) = hv;

    if (qd == 0 && t < DK) {
        float s2 = 0.0f;
#pragma unroll
        for (int s = 0; s < NSPLIT; s++)
            s2 += g_ks_part[(s * BH + bh) * DK + t];
        g_Ksum[bh * DK + t] = s2;
    }
}

// ---------------- attn_apply: z via extra mma column -------------------------
// grid (L/128 = 16, BH), 256 threads (8 warps, 16 rows each).
__global__ __launch_bounds__(256)
void attn_apply_kernel(const __half* __restrict__ Qp, __half* __restrict__ Mid)
{
    __shared__ __align__(16) __half Qs[128 * 64];
    __shared__ __align__(16) __half KVh[64 * 64];
    __shared__ __align__(4) __half Kssh[DK];

    const int lc = blockIdx.x;
    const int bh = blockIdx.y;
    const int b = bh >> 4;
    const int h = bh & 15;
    const int tid = threadIdx.x;
    const int w = tid >> 5;
    const int lane = tid & 31;
    const int gid = lane >> 2;
    const int tig = lane & 3;

    const __half* Qg = Qp + ((size_t)(b * L_SZ + lc * 128)) * DM + h * DK;
    const uint32_t qsb = su32(Qs);
    const uint32_t kvb = su32(KVh);

    // Q tile: 128 rows x 128B swizzled
#pragma unroll
    for (int j = 0; j < 4; j++) {
        int i = tid + j * 256;
        int r = i >> 3, q = i & 7;
        CP16(qsb + SWZ(r * 128 + q * 16), Qg + (size_t)r * DM + q * 8);
    }
    // KV tile: straight 8KB copy (already swizzled in global)
    {
        const char* KVg = (const char*)(g_KVh + (size_t)bh * (DK * DK));
#pragma unroll
        for (int j = 0; j < 2; j++) {
            int i = tid + j * 256;
            CP16(kvb + i * 16, KVg + i * 16);
        }
    }
    CP_COMMIT();
    if (tid < DK) Kssh[tid] = __float2half_rn(g_Ksum[bh * DK + tid]);
    asm volatile("cp.async.wait_group 0;");
    __syncthreads();

    float acc[8][4];
#pragma unroll
    for (int ni = 0; ni < 8; ni++)
#pragma unroll
        for (int c = 0; c < 4; c++) acc[ni][c] = 0.0f;
    float accz[4] = {0, 0, 0, 0};

    const int lrow = lane & 15;
    const int lhi  = (lane >> 4) << 4;
    const int trow = ((lane & 16) >> 1) + (lane & 7);
    const int tcol = (lane & 8) << 1;

#pragma unroll
    for (int ks = 0; ks < 4; ks++) {
        uint32_t af[4];
        ldm_x4(af, qsb + SWZ((w * 16 + lrow) * 128 + ks * 32 + lhi));
        uint32_t bf[4][4];
#pragma unroll
        for (int p = 0; p < 4; p++)
            ldm_x4_t(bf[p], kvb + SWZ((ks * 16 + trow) * 128 + p * 32 + tcol));
#pragma unroll
        for (int p = 0; p < 4; p++) {
            uint32_t b0[2] = { bf[p][0], bf[p][2] };
            uint32_t b1[2] = { bf[p][1], bf[p][3] };
            mma_f16(acc[2 * p + 0], af, b0);
            mma_f16(acc[2 * p + 1], af, b1);
        }
        // z mma: B column 0 = Ksum(fp16), other columns zero
        uint32_t bz[2] = { 0u, 0u };
        if (lane < 4) {
            __half2 hz0 = *(const __half2*)&Kssh[ks * 16 + lane * 2];
            __half2 hz1 = *(const __half2*)&Kssh[ks * 16 + 8 + lane * 2];
            bz[0] = *(uint32_t*)&hz0;
            bz[1] = *(uint32_t*)&hz1;
        }
        mma_f16(accz, af, bz);
    }

    // broadcast col-0 dot (tig==0 lanes) to all 4 lanes of each row group
    const float zr0 = __shfl_sync(0xffffffffu, accz[0], lane & ~3);
    const float zr1 = __shfl_sync(0xffffffffu, accz[2], lane & ~3);
    const float z0 = 1.0f / (zr0 + EPS_Z);
    const float z1 = 1.0f / (zr1 + EPS_Z);

    const int r0 = w * 16 + gid;               // 0..127
    __half* Og = Mid + ((size_t)(b * L_SZ + lc * 128)) * DM + h * DK;
#pragma unroll
    for (int ni = 0; ni < 8; ni++) {
        int c0 = ni * 8 + tig * 2;
        *(__half2*)&Og[(size_t)r0 * DM + c0] =
            __floats2half2_rn(acc[ni][0] * z0, acc[ni][1] * z0);
        *(__half2*)&Og[(size_t)(r0 + 8) * DM + c0] =
            __floats2half2_rn(acc[ni][2] * z1, acc[ni][3] * z1);
    }
}

// ---------------- launch -----------------------------------------------------
extern "C" void kernel_launch(void* const* d_in, const int* in_sizes, int n_in,
                              void* d_out, int out_size)
{
    const float* q  = (const float*)d_in[0];
    const float* k  = (const float*)d_in[1];
    const float* v  = (const float*)d_in[2];
    const float* wq = (const float*)d_in[4];
    const float* wk = (const float*)d_in[5];
    const float* wv = (const float*)d_in[6];
    const float* wo = (const float*)d_in[7];
    float* out = (float*)d_out;

    __half *Wh, *Ah, *Qp, *Kp, *Vp, *Mid;
    cudaGetSymbolAddress((void**)&Wh,  g_Wh);
    cudaGetSymbolAddress((void**)&Ah,  g_Ah);
    cudaGetSymbolAddress((void**)&Qp,  g_Qp);
    cudaGetSymbolAddress((void**)&Kp,  g_Kp);
    cudaGetSymbolAddress((void**)&Vp,  g_Vp);
    cudaGetSymbolAddress((void**)&Mid, g_Mid);

    cudaFuncSetAttribute(mega_proj, cudaFuncAttributeMaxDynamicSharedMemorySize, GSMEM);
    cudaFuncSetAttribute(gemm_out,  cudaFuncAttributeMaxDynamicSharedMemorySize, GSMEM);

    cvt_all<<<512 + 3 * 1024, 256>>>(q, k, v, wq, wk, wv, wo);

    mega_proj<<<2048, 256, GSMEM>>>(Ah, Wh, Qp, Kp, Vp);

    kv_combine_kernel<<<dim3(BH, 4), 256>>>();
    attn_apply_kernel<<<dim3(L_SZ / 128, BH), 256>>>(Qp, Mid);

    dim3 gf(DM / GBN, ROWS / GBM);          // (8, 64) = 512 blocks
    gemm_out<<<gf, 256, GSMEM>>>(Mid, Wh + 3 * (size_t)DM * DM, out);
}

// round 17
// speedup vs baseline: 1.0260x; 1.0089x over previous
#include <cuda_runtime.h>
#include <cuda_fp16.h>
#include <cstdint>

#define B_SZ 4
#define L_SZ 2048
#define DM   1024
#define H_N  16
#define DK   64
#define BH   64
#define ROWS 8192
#define EPS_Z 1e-8f
#define NSPLIT 8

// ---------------- scratch ----------------------------------------------------
__device__ __half g_Wh[4][DM * DM];
__device__ __half g_Ah[3][ROWS * DM];
__device__ __half g_Qp[ROWS * DM];
__device__ __half g_Kp[ROWS * DM];
__device__ __half g_Vp[ROWS * DM];
__device__ __half g_Mid[ROWS * DM];
__device__ float  g_kv_part[NSPLIT * BH * DK * DK];
__device__ float  g_ks_part[NSPLIT * BH * DK];
__device__ __half g_KVh[BH * DK * DK];     // fp16, pre-swizzled per head (8KB each)
__device__ float  g_Ksum[BH * DK];
__device__ unsigned int g_kv_done;
__device__ unsigned int g_cmb_done;
__device__ unsigned int g_row_done[64];

// ---------------- helpers ----------------------------------------------------
__device__ __forceinline__ float feature_map(float x) {
    return x > 0.0f ? x + 1.0f : expf(x);
}
__device__ __forceinline__ uint32_t su32(const void* p) {
    uint32_t a;
    asm("{ .reg .u64 t; cvta.to.shared.u64 t, %1; cvt.u32.u64 %0, t; }" : "=r"(a) : "l"(p));
    return a;
}
#define CP16(s, g) asm volatile("cp.async.cg.shared.global [%0], [%1], 16;" :: "r"(s), "l"(g))
#define CP_COMMIT() asm volatile("cp.async.commit_group;")
#define SWZ(o) ((o) ^ (((o) >> 3) & 0x70))

__device__ __forceinline__ void ldm_x4(uint32_t* r, uint32_t addr) {
    asm volatile("ldmatrix.sync.aligned.m8n8.x4.shared.b16 {%0,%1,%2,%3}, [%4];"
                 : "=r"(r[0]), "=r"(r[1]), "=r"(r[2]), "=r"(r[3]) : "r"(addr));
}
__device__ __forceinline__ void ldm_x4_t(uint32_t* r, uint32_t addr) {
    asm volatile("ldmatrix.sync.aligned.m8n8.x4.trans.shared.b16 {%0,%1,%2,%3}, [%4];"
                 : "=r"(r[0]), "=r"(r[1]), "=r"(r[2]), "=r"(r[3]) : "r"(addr));
}
__device__ __forceinline__ void mma_f16(float* d, const uint32_t* a, const uint32_t* b) {
    asm volatile(
        "mma.sync.aligned.m16n8k16.row.col.f32.f16.f16.f32 "
        "{%0,%1,%2,%3},{%4,%5,%6,%7},{%8,%9},{%0,%1,%2,%3};\n"
        : "+f"(d[0]), "+f"(d[1]), "+f"(d[2]), "+f"(d[3])
        : "r"(a[0]), "r"(a[1]), "r"(a[2]), "r"(a[3]),
          "r"(b[0]), "r"(b[1]));
}

// ---------------- fp16 GEMM core (R11): BM=128 BN=128 BK=64, 256 thr ---------
#define GBM 128
#define GBN 128
#define ABYTES (GBM * 128)
#define BBYTES (GBN * 128)
#define STAGEB (ABYTES + BBYTES)  // 32768
#define GSMEM  (2 * STAGEB)       // 65536

template <int OUTK>
__device__ __forceinline__
void gemm_core(const __half* __restrict__ A, const __half* __restrict__ W,
               void* __restrict__ Cv, int act, int bm0, int bn0, char* sm)
{
    const int tid = threadIdx.x;
    const int wid = tid >> 5;
    const int lane = tid & 31;
    const int wm = wid >> 1;
    const int wn = wid & 1;
    const int gid = lane >> 2;
    const int tig = lane & 3;

    const __half* Ag = A + (size_t)bm0 * DM;
    const __half* Wg = W + (size_t)bn0 * DM;
    const uint32_t sbase = su32(sm);

    float acc[2][8][4];
#pragma unroll
    for (int mi = 0; mi < 2; mi++)
#pragma unroll
        for (int ni = 0; ni < 8; ni++)
#pragma unroll
            for (int c = 0; c < 4; c++) acc[mi][ni][c] = 0.0f;

    auto load_tile = [&](int stg, int k0) {
        const uint32_t ab = sbase + stg * STAGEB;
        const uint32_t bb = ab + ABYTES;
#pragma unroll
        for (int j = 0; j < 4; j++) {
            int i = tid + j * 256;
            int r = i >> 3, q = i & 7;
            CP16(ab + SWZ(r * 128 + q * 16), Ag + (size_t)r * DM + k0 + q * 8);
        }
#pragma unroll
        for (int j = 0; j < 4; j++) {
            int i = tid + j * 256;
            int r = i >> 3, q = i & 7;
            CP16(bb + SWZ(r * 128 + q * 16), Wg + (size_t)r * DM + k0 + q * 8);
        }
        CP_COMMIT();
    };

    const int KT = DM / 64;
    load_tile(0, 0);

    const int lrow = lane & 15;
    const int lhi  = (lane >> 4) << 4;

    for (int t = 0; t < KT; t++) {
        const int cur = t & 1;
        if (t + 1 < KT) {
            load_tile(cur ^ 1, (t + 1) * 64);
            asm volatile("cp.async.wait_group 1;");
        } else {
            asm volatile("cp.async.wait_group 0;");
        }
        __syncthreads();

        const uint32_t ab = sbase + cur * STAGEB;
        const uint32_t bb = ab + ABYTES;

#pragma unroll
        for (int ks = 0; ks < 4; ks++) {
            const int kboff = ks * 32 + lhi;
            uint32_t af[2][4];
            uint32_t bf[4][4];
#pragma unroll
            for (int mi = 0; mi < 2; mi++)
                ldm_x4(af[mi], ab + SWZ((wm * 32 + mi * 16 + lrow) * 128 + kboff));
#pragma unroll
            for (int p = 0; p < 4; p++)
                ldm_x4(bf[p], bb + SWZ((wn * 64 + p * 16 + lrow) * 128 + kboff));
#pragma unroll
            for (int mi = 0; mi < 2; mi++)
#pragma unroll
                for (int p = 0; p < 4; p++) {
                    uint32_t b0[2] = { bf[p][0], bf[p][2] };
                    uint32_t b1[2] = { bf[p][1], bf[p][3] };
                    mma_f16(acc[mi][2 * p + 0], af[mi], b0);
                    mma_f16(acc[mi][2 * p + 1], af[mi], b1);
                }
        }
        __syncthreads();
    }

#pragma unroll
    for (int mi = 0; mi < 2; mi++) {
        int r0 = bm0 + wm * 32 + mi * 16 + gid;
#pragma unroll
        for (int ni = 0; ni < 8; ni++) {
            int c0 = bn0 + wn * 64 + ni * 8 + tig * 2;
            float v0 = acc[mi][ni][0];
            float v1 = acc[mi][ni][1];
            float v2 = acc[mi][ni][2];
            float v3 = acc[mi][ni][3];
            if (act) {
                v0 = feature_map(v0); v1 = feature_map(v1);
                v2 = feature_map(v2); v3 = feature_map(v3);
            }
            if (OUTK) {
                __half* C = (__half*)Cv;
                *(__half2*)&C[(size_t)r0 * DM + c0]       = __floats2half2_rn(v0, v1);
                *(__half2*)&C[(size_t)(r0 + 8) * DM + c0] = __floats2half2_rn(v2, v3);
            } else {
                float* C = (float*)Cv;
                *(float2*)&C[(size_t)r0 * DM + c0]       = make_float2(v0, v1);
                *(float2*)&C[(size_t)(r0 + 8) * DM + c0] = make_float2(v2, v3);
            }
        }
    }
}

// ---------------- kv_partial body (256 threads; compute on warps 0-3) --------
__device__ __forceinline__
void kv_partial_body(const __half* __restrict__ Kp, const __half* __restrict__ Vp,
                     int s, int bh, char* sm)
{
    const int tid = threadIdx.x;
    const int w = tid >> 5;
    const int lane = tid & 31;
    const int gid = lane >> 2;
    const int tig = lane & 3;
    const int b = bh >> 4;
    const int h = bh & 15;

    const size_t rb = ((size_t)(b * L_SZ + s * (L_SZ / NSPLIT))) * DM + h * DK;
    const __half* Kg = Kp + rb;
    const __half* Vg = Vp + rb;

    const uint32_t base = su32(sm);
    const uint32_t ksb[2] = { base,         base + 16384 };
    const uint32_t vsb[2] = { base + 8192,  base + 24576 };

    auto load_chunk = [&](int buf, int n0) {
#pragma unroll
        for (int j = 0; j < 2; j++) {
            int i = tid + j * 256;
            int r = i >> 3, q = i & 7;
            CP16(ksb[buf] + SWZ(r * 128 + q * 16), Kg + (size_t)(n0 + r) * DM + q * 8);
            CP16(vsb[buf] + SWZ(r * 128 + q * 16), Vg + (size_t)(n0 + r) * DM + q * 8);
        }
        CP_COMMIT();
    };

    float accv[8][4];
#pragma unroll
    for (int ni = 0; ni < 8; ni++)
#pragma unroll
        for (int c = 0; c < 4; c++) accv[ni][c] = 0.0f;
    float accs[4] = {0, 0, 0, 0};

    const int trow = ((lane & 16) >> 1) + (lane & 7);
    const int tcol = (lane & 8) << 1;
    const uint32_t ONES2 = 0x3C003C00u;

    load_chunk(0, 0);

    for (int ch = 0; ch < 4; ch++) {
        const int cur = ch & 1;
        if (ch < 3) {
            load_chunk(cur ^ 1, (ch + 1) * 64);
            asm volatile("cp.async.wait_group 1;");
        } else {
            asm volatile("cp.async.wait_group 0;");
        }
        __syncthreads();

        if (w < 4) {
#pragma unroll
            for (int kk = 0; kk < 4; kk++) {
                uint32_t af[4];
                ldm_x4_t(af, ksb[cur] + SWZ((kk * 16 + trow) * 128 + w * 32 + tcol));
                uint32_t bf[4][4];
#pragma unroll
                for (int p = 0; p < 4; p++)
                    ldm_x4_t(bf[p], vsb[cur] + SWZ((kk * 16 + trow) * 128 + p * 32 + tcol));
#pragma unroll
                for (int p = 0; p < 4; p++) {
                    uint32_t b0[2] = { bf[p][0], bf[p][2] };
                    uint32_t b1[2] = { bf[p][1], bf[p][3] };
                    mma_f16(accv[2 * p + 0], af, b0);
                    mma_f16(accv[2 * p + 1], af, b1);
                }
                uint32_t bo[2] = { ONES2, ONES2 };
                mma_f16(accs, af, bo);
            }
        }
        __syncthreads();
    }

    if (w < 4) {
        float* outp = g_kv_part + ((size_t)(s * BH + bh)) * (DK * DK);
        const int r0 = w * 16 + gid;
#pragma unroll
        for (int ni = 0; ni < 8; ni++) {
            int c0 = ni * 8 + tig * 2;
            *(float2*)&outp[r0 * DK + c0]       = make_float2(accv[ni][0], accv[ni][1]);
            *(float2*)&outp[(r0 + 8) * DK + c0] = make_float2(accv[ni][2], accv[ni][3]);
        }
        if (tig == 0) {
            g_ks_part[(s * BH + bh) * DK + r0]     = accs[0];
            g_ks_part[(s * BH + bh) * DK + r0 + 8] = accs[2];
        }
    }
}

// ---------------- mega launch 1: K/V GEMMs + Q GEMM + kv_partial -------------
__global__ __launch_bounds__(256, 2)
void mega_proj(const __half* __restrict__ Ah, const __half* __restrict__ Wh,
               __half* __restrict__ Qp, __half* __restrict__ Kp, __half* __restrict__ Vp)
{
    extern __shared__ __align__(16) char sm[];
    const int b = blockIdx.x;
    if (b < 1024) {
        const int z = b >> 9;                   // 0 -> K, 1 -> V
        const int bb = b & 511;
        const __half* A = Ah + (size_t)(z + 1) * ROWS * DM;
        const __half* W = Wh + (size_t)(z + 1) * DM * DM;
        __half* C = (z == 0) ? Kp : Vp;
        gemm_core<1>(A, W, (void*)C, z == 0 ? 1 : 0,
                     (bb >> 3) * GBM, (bb & 7) * GBN, sm);
        __threadfence();
        __syncthreads();
        if (threadIdx.x == 0) atomicAdd(&g_kv_done, 1u);
    } else if (b < 1536) {
        const int bb = b - 1024;
        gemm_core<1>(Ah, Wh, (void*)Qp, 1, (bb >> 3) * GBM, (bb & 7) * GBN, sm);
    } else {
        if (threadIdx.x == 0) {
            while (atomicAdd(&g_kv_done, 0u) < 1024u) { }
        }
        __syncthreads();
        const int idx = b - 1536;
        kv_partial_body(Kp, Vp, idx & (NSPLIT - 1), idx >> 3, sm);
    }
}

// ---------------- bodies for the fused tail ----------------------------------
__device__ __forceinline__
void kv_combine_body(int bh, int qd)
{
    const int t = threadIdx.x;
    const int e4 = qd * 256 + t;                 // 0..1023
    float4 sum = {0, 0, 0, 0};
#pragma unroll
    for (int s = 0; s < NSPLIT; s++) {
        float4 p = ((const float4*)(g_kv_part + ((size_t)(s * BH + bh)) * (DK * DK)))[e4];
        sum.x += p.x; sum.y += p.y; sum.z += p.z; sum.w += p.w;
    }
    const int d = e4 >> 4;
    const int boff = d * 128 + (e4 & 15) * 8;
    uint2 hv;
    __half2 h0 = __floats2half2_rn(sum.x, sum.y);
    __half2 h1 = __floats2half2_rn(sum.z, sum.w);
    hv.x = *(uint32_t*)&h0;
    hv.y = *(uint32_t*)&h1;
    *(uint2*)((char*)(g_KVh + (size_t)bh * (DK * DK)) + SWZ(boff)) = hv;

    if (qd == 0 && t < DK) {
        float s2 = 0.0f;
#pragma unroll
        for (int s = 0; s < NSPLIT; s++)
            s2 += g_ks_part[(s * BH + bh) * DK + t];
        g_Ksum[bh * DK + t] = s2;
    }
}

// attn body: dynamic smem layout  [Qs 16KB][KVh 8KB][Kssh 128B]
__device__ __forceinline__
void attn_body(const __half* __restrict__ Qp, __half* __restrict__ Mid,
               int lc, int bh, char* sm)
{
    const int tid = threadIdx.x;
    const int w = tid >> 5;
    const int lane = tid & 31;
    const int gid = lane >> 2;
    const int tig = lane & 3;
    const int b = bh >> 4;
    const int h = bh & 15;

    const uint32_t qsb = su32(sm);
    const uint32_t kvb = qsb + 16384;
    __half* Kssh = (__half*)(sm + 24576);

    const __half* Qg = Qp + ((size_t)(b * L_SZ + lc * 128)) * DM + h * DK;

    // Q tile prefetch (no dependency) — issued by caller BEFORE the spin.
#pragma unroll
    for (int j = 0; j < 4; j++) {
        int i = tid + j * 256;
        int r = i >> 3, q = i & 7;
        CP16(qsb + SWZ(r * 128 + q * 16), Qg + (size_t)r * DM + q * 8);
    }
    CP_COMMIT();

    // spin for combine completion
    if (tid == 0) {
        while (atomicAdd(&g_cmb_done, 0u) < 256u) { }
    }
    __syncthreads();

    // KV tile: straight 8KB copy (pre-swizzled in global)
    {
        const char* KVg = (const char*)(g_KVh + (size_t)bh * (DK * DK));
#pragma unroll
        for (int j = 0; j < 2; j++) {
            int i = tid + j * 256;
            CP16(kvb + i * 16, KVg + i * 16);
        }
    }
    CP_COMMIT();
    if (tid < DK) Kssh[tid] = __float2half_rn(__ldcg(&g_Ksum[bh * DK + tid]));
    asm volatile("cp.async.wait_group 0;");
    __syncthreads();

    float acc[8][4];
#pragma unroll
    for (int ni = 0; ni < 8; ni++)
#pragma unroll
        for (int c = 0; c < 4; c++) acc[ni][c] = 0.0f;
    float accz[4] = {0, 0, 0, 0};

    const int lrow = lane & 15;
    const int lhi  = (lane >> 4) << 4;
    const int trow = ((lane & 16) >> 1) + (lane & 7);
    const int tcol = (lane & 8) << 1;

#pragma unroll
    for (int ks = 0; ks < 4; ks++) {
        uint32_t af[4];
        ldm_x4(af, qsb + SWZ((w * 16 + lrow) * 128 + ks * 32 + lhi));
        uint32_t bf[4][4];
#pragma unroll
        for (int p = 0; p < 4; p++)
            ldm_x4_t(bf[p], kvb + SWZ((ks * 16 + trow) * 128 + p * 32 + tcol));
#pragma unroll
        for (int p = 0; p < 4; p++) {
            uint32_t b0[2] = { bf[p][0], bf[p][2] };
            uint32_t b1[2] = { bf[p][1], bf[p][3] };
            mma_f16(acc[2 * p + 0], af, b0);
            mma_f16(acc[2 * p + 1], af, b1);
        }
        uint32_t bz[2] = { 0u, 0u };
        if (lane < 4) {
            __half2 hz0 = *(const __half2*)&Kssh[ks * 16 + lane * 2];
            __half2 hz1 = *(const __half2*)&Kssh[ks * 16 + 8 + lane * 2];
            bz[0] = *(uint32_t*)&hz0;
            bz[1] = *(uint32_t*)&hz1;
        }
        mma_f16(accz, af, bz);
    }

    const float zr0 = __shfl_sync(0xffffffffu, accz[0], lane & ~3);
    const float zr1 = __shfl_sync(0xffffffffu, accz[2], lane & ~3);
    const float z0 = 1.0f / (zr0 + EPS_Z);
    const float z1 = 1.0f / (zr1 + EPS_Z);

    const int r0 = w * 16 + gid;
    __half* Og = Mid + ((size_t)(b * L_SZ + lc * 128)) * DM + h * DK;
#pragma unroll
    for (int ni = 0; ni < 8; ni++) {
        int c0 = ni * 8 + tig * 2;
        *(__half2*)&Og[(size_t)r0 * DM + c0] =
            __floats2half2_rn(acc[ni][0] * z0, acc[ni][1] * z0);
        *(__half2*)&Og[(size_t)(r0 + 8) * DM + c0] =
            __floats2half2_rn(acc[ni][2] * z1, acc[ni][3] * z1);
    }
}

// ---------------- mega launch 2: combine + attn + out-projection -------------
// blocks [0,256): combine; [256,1280): attn; [1280,1792): out GEMM.
__global__ __launch_bounds__(256, 2)
void mega_tail(const __half* __restrict__ Qp, __half* __restrict__ Mid,
               const __half* __restrict__ Wo, float* __restrict__ out)
{
    extern __shared__ __align__(16) char sm[];
    const int b = blockIdx.x;
    if (b < 256) {
        kv_combine_body(b >> 2, b & 3);
        __threadfence();
        __syncthreads();
        if (threadIdx.x == 0) atomicAdd(&g_cmb_done, 1u);
    } else if (b < 1280) {
        const int idx = b - 256;
        const int bh = idx >> 4;
        const int lc = idx & 15;
        attn_body(Qp, Mid, lc, bh, sm);
        __threadfence();
        __syncthreads();
        if (threadIdx.x == 0) {
            const int bt = (bh >> 4) * 16 + lc;   // row-tile 0..63
            atomicAdd(&g_row_done[bt], 1u);
        }
    } else {
        const int bb = b - 1280;
        const int bt = bb >> 3;
        if (threadIdx.x == 0) {
            while (atomicAdd(&g_row_done[bt], 0u) < 16u) { }
        }
        __syncthreads();
        gemm_core<0>(Mid, Wo, (void*)out, 0, bt * GBM, (bb & 7) * GBN, sm);
    }
}

// ---------------- single fused fp32 -> fp16 convert (+ counter resets) -------
__global__ __launch_bounds__(256)
void cvt_all(const float* __restrict__ q, const float* __restrict__ k,
             const float* __restrict__ v,
             const float* __restrict__ w0, const float* __restrict__ w1,
             const float* __restrict__ w2, const float* __restrict__ w3)
{
    const int b = blockIdx.x;
    if (b == 0) {
        if (threadIdx.x == 0) { g_kv_done = 0; g_cmb_done = 0; }
        if (threadIdx.x < 64) g_row_done[threadIdx.x] = 0;
    }
    const float* in;
    __half* out;
    int base;
    if (b < 512) {
        const float* wsrc[4] = { w0, w1, w2, w3 };
        int w = b >> 7;
        in = wsrc[w];
        out = g_Wh[w];
        base = (b & 127) * 2048;
    } else {
        const float* asrc[3] = { q, k, v };
        int r = b - 512;
        int z = r >> 10;
        in = asrc[z];
        out = g_Ah[z];
        base = (r & 1023) * 2048;
    }
#pragma unroll
    for (int j = 0; j < 8; j++) {
        int i = base + j * 256 + threadIdx.x;
        float4 x = ((const float4*)in)[i];
        ((__half2*)out)[2 * i]     = __floats2half2_rn(x.x, x.y);
        ((__half2*)out)[2 * i + 1] = __floats2half2_rn(x.z, x.w);
    }
}

// ---------------- launch -----------------------------------------------------
extern "C" void kernel_launch(void* const* d_in, const int* in_sizes, int n_in,
                              void* d_out, int out_size)
{
    const float* q  = (const float*)d_in[0];
    const float* k  = (const float*)d_in[1];
    const float* v  = (const float*)d_in[2];
    const float* wq = (const float*)d_in[4];
    const float* wk = (const float*)d_in[5];
    const float* wv = (const float*)d_in[6];
    const float* wo = (const float*)d_in[7];
    float* out = (float*)d_out;

    __half *Wh, *Ah, *Qp, *Kp, *Vp, *Mid;
    cudaGetSymbolAddress((void**)&Wh,  g_Wh);
    cudaGetSymbolAddress((void**)&Ah,  g_Ah);
    cudaGetSymbolAddress((void**)&Qp,  g_Qp);
    cudaGetSymbolAddress((void**)&Kp,  g_Kp);
    cudaGetSymbolAddress((void**)&Vp,  g_Vp);
    cudaGetSymbolAddress((void**)&Mid, g_Mid);

    cudaFuncSetAttribute(mega_proj, cudaFuncAttributeMaxDynamicSharedMemorySize, GSMEM);
    cudaFuncSetAttribute(mega_tail, cudaFuncAttributeMaxDynamicSharedMemorySize, GSMEM);

    cvt_all<<<512 + 3 * 1024, 256>>>(q, k, v, wq, wk, wv, wo);

    mega_proj<<<2048, 256, GSMEM>>>(Ah, Wh, Qp, Kp, Vp);

    mega_tail<<<1792, 256, GSMEM>>>(Qp, Mid, Wh + 3 * (size_t)DM * DM, out);
}